// round 5
// baseline (speedup 1.0000x reference)
#include <cuda_runtime.h>
#include <cstdint>

#define NN   100000
#define NE   1600000
#define FEAT 256
#define HID  128
#define OUTC 64
#define NB   10000
#define EPSV 1e-5f

#define NSB  ((NN + 511) / 512)   // 196 scan blocks

// ---------------- device scratch (static, allocation-free) ----------------
__device__ int   g_deg[NN];
__device__ float g_dinv[NN];
__device__ int   g_rowstart[NN + 1];
__device__ int   g_cursor[NN];
__device__ int   g_col[NE];
__device__ int   g_blocksums[NSB];
__device__ int   g_blockoffs[NSB];
__device__ float g_h1[(size_t)NN * HID];   // dinv-prescaled X@W1
__device__ float g_p1[(size_t)NN * HID];   // propagated layer1 (pre-BN)
__device__ float g_h2[(size_t)NN * OUTC];
__device__ float g_p2[(size_t)NN * OUTC];
__device__ float g_stats1[2 * HID];        // [sum | sumsq]
__device__ float g_stats2[2 * OUTC];

// ---------------- degree / CSR build ----------------
__global__ void k_init() {
    int i = blockIdx.x * blockDim.x + threadIdx.x;
    if (i < NN) g_deg[i] = 1;              // self loop
    if (i < 2 * HID)  g_stats1[i] = 0.f;
    if (i < 2 * OUTC) g_stats2[i] = 0.f;
}

__global__ void k_count(const int* __restrict__ dst) {
    int e = blockIdx.x * blockDim.x + threadIdx.x;
    if (e < NE) atomicAdd(&g_deg[dst[e]], 1);
}

__global__ void k_dinv() {
    int i = blockIdx.x * blockDim.x + threadIdx.x;
    if (i < NN) g_dinv[i] = rsqrtf((float)g_deg[i]);
}

__global__ void k_scan_a() {
    __shared__ int s[512];
    int t = threadIdx.x;
    int i = blockIdx.x * 512 + t;
    int v = (i < NN) ? (g_deg[i] - 1) : 0;   // CSR counts exclude self loop
    s[t] = v;
    __syncthreads();
    #pragma unroll
    for (int off = 1; off < 512; off <<= 1) {
        int x = 0;
        if (t >= off) x = s[t - off];
        __syncthreads();
        s[t] += x;
        __syncthreads();
    }
    if (i < NN) g_rowstart[i] = s[t] - v;    // exclusive within block
    if (t == 511) g_blocksums[blockIdx.x] = s[511];
}

__global__ void k_scan_b() {
    __shared__ int s[256];
    int t = threadIdx.x;
    int v = (t < NSB) ? g_blocksums[t] : 0;
    s[t] = v;
    __syncthreads();
    #pragma unroll
    for (int off = 1; off < 256; off <<= 1) {
        int x = 0;
        if (t >= off) x = s[t - off];
        __syncthreads();
        s[t] += x;
        __syncthreads();
    }
    if (t < NSB) g_blockoffs[t] = s[t] - v;
}

__global__ void k_scan_c() {
    int t = threadIdx.x;
    int b = blockIdx.x;
    int i = b * 512 + t;
    if (i < NN) {
        int r = g_rowstart[i] + g_blockoffs[b];
        g_rowstart[i] = r;
        g_cursor[i] = r;
    }
    if (i == 0) g_rowstart[NN] = NE;
}

__global__ void k_fill(const int* __restrict__ src, const int* __restrict__ dst) {
    int e = blockIdx.x * blockDim.x + threadIdx.x;
    if (e >= NE) return;
    int d = dst[e];
    int p = atomicAdd(&g_cursor[d], 1);
    g_col[p] = src[e];
}

// ---------------- GEMM1: g_h1 = dinv[row] * (X @ W1) ----------------
// 128x128 block tile, BK=16, 256 threads, 8x8 per-thread microtile
__global__ __launch_bounds__(256) void k_gemm1(const float* __restrict__ X,
                                               const float* __restrict__ W) {
    __shared__ float As[16][128];   // [k][m]
    __shared__ float Bs[16][128];   // [k][n]
    const int bm  = blockIdx.x * 128;
    const int tid = threadIdx.x;
    const int tx  = tid & 15, ty = tid >> 4;
    float acc[8][8];
    #pragma unroll
    for (int i = 0; i < 8; i++)
        #pragma unroll
        for (int j = 0; j < 8; j++) acc[i][j] = 0.f;

    for (int k0 = 0; k0 < FEAT; k0 += 16) {
        #pragma unroll
        for (int l = 0; l < 2; l++) {
            int idx = tid + l * 256;
            int row = idx & 127;
            int kq  = (idx >> 7) * 4;
            float4 a = make_float4(0.f, 0.f, 0.f, 0.f);
            int gr = bm + row;
            if (gr < NN) a = *(const float4*)(X + (size_t)gr * FEAT + k0 + kq);
            As[kq + 0][row] = a.x; As[kq + 1][row] = a.y;
            As[kq + 2][row] = a.z; As[kq + 3][row] = a.w;
            int kr = idx >> 5, c4 = (idx & 31) * 4;
            *(float4*)&Bs[kr][c4] = *(const float4*)(W + (size_t)(k0 + kr) * HID + c4);
        }
        __syncthreads();
        #pragma unroll
        for (int kk = 0; kk < 16; kk++) {
            float a[8], b[8];
            *(float4*)&a[0] = *(const float4*)&As[kk][ty * 8];
            *(float4*)&a[4] = *(const float4*)&As[kk][ty * 8 + 4];
            *(float4*)&b[0] = *(const float4*)&Bs[kk][tx * 8];
            *(float4*)&b[4] = *(const float4*)&Bs[kk][tx * 8 + 4];
            #pragma unroll
            for (int i = 0; i < 8; i++)
                #pragma unroll
                for (int j = 0; j < 8; j++) acc[i][j] = fmaf(a[i], b[j], acc[i][j]);
        }
        __syncthreads();
    }
    #pragma unroll
    for (int i = 0; i < 8; i++) {
        int gr = bm + ty * 8 + i;
        if (gr >= NN) break;
        float dv = g_dinv[gr];
        #pragma unroll
        for (int j = 0; j < 8; j += 4) {
            float4 o;
            o.x = acc[i][j + 0] * dv; o.y = acc[i][j + 1] * dv;
            o.z = acc[i][j + 2] * dv; o.w = acc[i][j + 3] * dv;
            *(float4*)(g_h1 + (size_t)gr * HID + tx * 8 + j) = o;
        }
    }
}

// ---------------- propagate layer1: warp per node, float4 lanes ----------------
__global__ void k_prop128(const float* __restrict__ bias) {
    int gt = blockIdx.x * blockDim.x + threadIdx.x;
    int v = gt >> 5;
    if (v >= NN) return;
    int lane = gt & 31;
    const float4* hp = (const float4*)g_h1;
    float4 acc = hp[(size_t)v * 32 + lane];        // self loop (prescaled)
    int beg = g_rowstart[v], end = g_rowstart[v + 1];
    for (int j = beg; j < end; j++) {
        int s = __ldg(&g_col[j]);
        float4 x = hp[(size_t)s * 32 + lane];
        acc.x += x.x; acc.y += x.y; acc.z += x.z; acc.w += x.w;
    }
    float dv = g_dinv[v];
    float4 b = ((const float4*)bias)[lane];
    float4 o;
    o.x = fmaf(acc.x, dv, b.x); o.y = fmaf(acc.y, dv, b.y);
    o.z = fmaf(acc.z, dv, b.z); o.w = fmaf(acc.w, dv, b.w);
    ((float4*)g_p1)[(size_t)v * 32 + lane] = o;
}

// ---------------- BN stats over p1 (sum, sumsq per channel) ----------------
__global__ void k_stats1() {
    const int C = HID, RPB = 256 / C;      // 2 rows per block-iter
    int c = threadIdx.x % C;
    int rsub = threadIdx.x / C;
    float s = 0.f, ss = 0.f;
    for (int r = blockIdx.x * RPB + rsub; r < NN; r += gridDim.x * RPB) {
        float v = g_p1[(size_t)r * C + c];
        s += v; ss += v * v;
    }
    __shared__ float sh[256], sh2[256];
    sh[threadIdx.x] = s; sh2[threadIdx.x] = ss;
    __syncthreads();
    if (rsub == 0) {
        #pragma unroll
        for (int k = 1; k < RPB; k++) { s += sh[k * C + c]; ss += sh2[k * C + c]; }
        atomicAdd(&g_stats1[c], s);
        atomicAdd(&g_stats1[C + c], ss);
    }
}

// ---------------- GEMM2: g_h2 = dinv[row] * (relu(BN1(p1)) @ W2) ----------------
__global__ __launch_bounds__(256) void k_gemm2(const float* __restrict__ W2,
                                               const float* __restrict__ gamma1,
                                               const float* __restrict__ beta1) {
    __shared__ float As[16][128];   // [k][m]
    __shared__ float Bs[16][64];    // [k][n]
    __shared__ float bnA[HID], bnB[HID];
    const int tid = threadIdx.x;
    if (tid < HID) {
        float s  = g_stats1[tid], ss = g_stats1[HID + tid];
        float mu = s * (1.0f / NN);
        float var = ss * (1.0f / NN) - mu * mu;
        float rs = rsqrtf(var + EPSV);
        float ga = gamma1[tid];
        bnA[tid] = rs * ga;
        bnB[tid] = beta1[tid] - mu * rs * ga;
    }
    __syncthreads();
    const int bm = blockIdx.x * 128;
    const int tx = tid & 15, ty = tid >> 4;   // cols tx*4, rows ty*8
    float acc[8][4];
    #pragma unroll
    for (int i = 0; i < 8; i++)
        #pragma unroll
        for (int j = 0; j < 4; j++) acc[i][j] = 0.f;

    for (int k0 = 0; k0 < HID; k0 += 16) {
        #pragma unroll
        for (int l = 0; l < 2; l++) {
            int idx = tid + l * 256;
            int row = idx & 127;
            int kq  = (idx >> 7) * 4;
            float4 a = make_float4(0.f, 0.f, 0.f, 0.f);
            int gr = bm + row;
            if (gr < NN) {
                a = *(const float4*)(g_p1 + (size_t)gr * HID + k0 + kq);
                a.x = fmaxf(0.f, fmaf(a.x, bnA[k0 + kq + 0], bnB[k0 + kq + 0]));
                a.y = fmaxf(0.f, fmaf(a.y, bnA[k0 + kq + 1], bnB[k0 + kq + 1]));
                a.z = fmaxf(0.f, fmaf(a.z, bnA[k0 + kq + 2], bnB[k0 + kq + 2]));
                a.w = fmaxf(0.f, fmaf(a.w, bnA[k0 + kq + 3], bnB[k0 + kq + 3]));
            }
            As[kq + 0][row] = a.x; As[kq + 1][row] = a.y;
            As[kq + 2][row] = a.z; As[kq + 3][row] = a.w;
        }
        {   // B tile: 16x64 = 256 float4, one per thread
            int kr = tid >> 4, c4 = (tid & 15) * 4;
            *(float4*)&Bs[kr][c4] = *(const float4*)(W2 + (size_t)(k0 + kr) * OUTC + c4);
        }
        __syncthreads();
        #pragma unroll
        for (int kk = 0; kk < 16; kk++) {
            float a[8], b[4];
            *(float4*)&a[0] = *(const float4*)&As[kk][ty * 8];
            *(float4*)&a[4] = *(const float4*)&As[kk][ty * 8 + 4];
            *(float4*)&b[0] = *(const float4*)&Bs[kk][tx * 4];
            #pragma unroll
            for (int i = 0; i < 8; i++)
                #pragma unroll
                for (int j = 0; j < 4; j++) acc[i][j] = fmaf(a[i], b[j], acc[i][j]);
        }
        __syncthreads();
    }
    #pragma unroll
    for (int i = 0; i < 8; i++) {
        int gr = bm + ty * 8 + i;
        if (gr >= NN) break;
        float dv = g_dinv[gr];
        float4 o;
        o.x = acc[i][0] * dv; o.y = acc[i][1] * dv;
        o.z = acc[i][2] * dv; o.w = acc[i][3] * dv;
        *(float4*)(g_h2 + (size_t)gr * OUTC + tx * 4) = o;
    }
}

// ---------------- propagate layer2: warp per node, float2 lanes ----------------
__global__ void k_prop64(const float* __restrict__ bias) {
    int gt = blockIdx.x * blockDim.x + threadIdx.x;
    int v = gt >> 5;
    if (v >= NN) return;
    int lane = gt & 31;
    const float2* hp = (const float2*)g_h2;
    float2 acc = hp[(size_t)v * 32 + lane];
    int beg = g_rowstart[v], end = g_rowstart[v + 1];
    for (int j = beg; j < end; j++) {
        int s = __ldg(&g_col[j]);
        float2 x = hp[(size_t)s * 32 + lane];
        acc.x += x.x; acc.y += x.y;
    }
    float dv = g_dinv[v];
    float2 b = ((const float2*)bias)[lane];
    float2 o;
    o.x = fmaf(acc.x, dv, b.x); o.y = fmaf(acc.y, dv, b.y);
    ((float2*)g_p2)[(size_t)v * 32 + lane] = o;
}

__global__ void k_stats2() {
    const int C = OUTC, RPB = 256 / C;     // 4 rows per block-iter
    int c = threadIdx.x % C;
    int rsub = threadIdx.x / C;
    float s = 0.f, ss = 0.f;
    for (int r = blockIdx.x * RPB + rsub; r < NN; r += gridDim.x * RPB) {
        float v = g_p2[(size_t)r * C + c];
        s += v; ss += v * v;
    }
    __shared__ float sh[256], sh2[256];
    sh[threadIdx.x] = s; sh2[threadIdx.x] = ss;
    __syncthreads();
    if (rsub == 0) {
        #pragma unroll
        for (int k = 1; k < RPB; k++) { s += sh[k * C + c]; ss += sh2[k * C + c]; }
        atomicAdd(&g_stats2[c], s);
        atomicAdd(&g_stats2[C + c], ss);
    }
}

// ---------------- final: gather batch, BN2+relu+log_softmax ----------------
__global__ void k_final(const int* __restrict__ bn,
                        const float* __restrict__ gamma2,
                        const float* __restrict__ beta2,
                        float* __restrict__ out) {
    int gt = blockIdx.x * blockDim.x + threadIdx.x;
    int w = gt >> 5;
    if (w >= NB) return;
    int lane = gt & 31;
    int node = bn[w];
    float2 v = ((const float2*)g_p2)[(size_t)node * 32 + lane];
    int c0 = lane * 2, c1 = c0 + 1;
    float x0, x1;
    {
        float s = g_stats2[c0], ss = g_stats2[OUTC + c0];
        float mu = s * (1.f / NN);
        float var = ss * (1.f / NN) - mu * mu;
        float rs = rsqrtf(var + EPSV);
        x0 = fmaxf(0.f, (v.x - mu) * rs * gamma2[c0] + beta2[c0]);
    }
    {
        float s = g_stats2[c1], ss = g_stats2[OUTC + c1];
        float mu = s * (1.f / NN);
        float var = ss * (1.f / NN) - mu * mu;
        float rs = rsqrtf(var + EPSV);
        x1 = fmaxf(0.f, (v.y - mu) * rs * gamma2[c1] + beta2[c1]);
    }
    float m = fmaxf(x0, x1);
    #pragma unroll
    for (int o = 16; o; o >>= 1) m = fmaxf(m, __shfl_xor_sync(0xffffffffu, m, o));
    float e = expf(x0 - m) + expf(x1 - m);
    #pragma unroll
    for (int o = 16; o; o >>= 1) e += __shfl_xor_sync(0xffffffffu, e, o);
    float l = m + logf(e);
    float2 r;
    r.x = x0 - l; r.y = x1 - l;
    ((float2*)out)[(size_t)w * 32 + lane] = r;
}

// ---------------- launch ----------------
extern "C" void kernel_launch(void* const* d_in, const int* in_sizes, int n_in,
                              void* d_out, int out_size) {
    const float* features = (const float*)d_in[0];
    const int*   ei       = (const int*)d_in[1];
    const int*   batch    = (const int*)d_in[2];
    const float* W1       = (const float*)d_in[3];
    const float* b1       = (const float*)d_in[4];
    const float* gamma1   = (const float*)d_in[5];
    const float* beta1    = (const float*)d_in[6];
    const float* W2       = (const float*)d_in[7];
    const float* b2       = (const float*)d_in[8];
    const float* gamma2   = (const float*)d_in[9];
    const float* beta2    = (const float*)d_in[10];
    const int* src = ei;
    const int* dst = ei + NE;
    float* out = (float*)d_out;

    k_init  <<<(NN + 255) / 256, 256>>>();
    k_count <<<(NE + 255) / 256, 256>>>(dst);
    k_dinv  <<<(NN + 255) / 256, 256>>>();
    k_scan_a<<<NSB, 512>>>();
    k_scan_b<<<1, 256>>>();
    k_scan_c<<<NSB, 512>>>();
    k_fill  <<<(NE + 255) / 256, 256>>>(src, dst);

    k_gemm1  <<<(NN + 127) / 128, 256>>>(features, W1);
    k_prop128<<<(NN * 32) / 256, 256>>>(b1);
    k_stats1 <<<256, 256>>>();

    k_gemm2  <<<(NN + 127) / 128, 256>>>(W2, gamma1, beta1);
    k_prop64 <<<(NN * 32) / 256, 256>>>(b2);
    k_stats2 <<<256, 256>>>();

    k_final  <<<(NB * 32) / 256, 256>>>(batch, gamma2, beta2, out);
}

// round 11
// speedup vs baseline: 1.3184x; 1.3184x over previous
#include <cuda_runtime.h>
#include <cuda_bf16.h>
#include <cstdint>

#define NN   100000
#define NE   1600000
#define FEAT 256
#define HID  128
#define OUTC 64
#define NB   10000
#define EPSV 1e-5f

#define NSB  ((NN + 511) / 512)   // 196 scan blocks

// ---------------- device scratch (static, allocation-free) ----------------
__device__ int   g_deg[NN];
__device__ float g_dinv[NN];
__device__ int   g_rowstart[NN + 1];
__device__ int   g_cursor[NN];
__device__ int   g_col[NE];
__device__ int   g_blocksums[NSB];
__device__ int   g_blockoffs[NSB];
__device__ float g_h1[(size_t)NN * HID];   // dinv-prescaled X@W1
__device__ float g_p1[(size_t)NN * HID];   // propagated layer1 (pre-BN)
__device__ float g_h2[(size_t)NN * OUTC];
__device__ float g_p2[(size_t)NN * OUTC];
__device__ float g_stats1[2 * HID];        // [sum | sumsq]
__device__ float g_stats2[2 * OUTC];

// ================= warp-MMA helpers (arch-neutral: ldmatrix + mma.sync) ======
__device__ __forceinline__ uint32_t smem_u32(const void* p) {
    uint32_t a;
    asm("{ .reg .u64 t; cvta.to.shared.u64 t, %1; cvt.u32.u64 %0, t; }" : "=r"(a) : "l"(p));
    return a;
}

#define LDSM4(r, addr)                                                          \
    asm volatile("ldmatrix.sync.aligned.m8n8.x4.shared.b16 {%0,%1,%2,%3}, [%4];"\
        : "=r"((r)[0]), "=r"((r)[1]), "=r"((r)[2]), "=r"((r)[3]) : "r"(addr))

#define MMAB(d, a, b0, b1)                                                      \
    asm volatile("mma.sync.aligned.m16n8k16.row.col.f32.bf16.bf16.f32 "         \
        "{%0,%1,%2,%3},{%4,%5,%6,%7},{%8,%9},{%0,%1,%2,%3};"                    \
        : "+f"((d)[0]), "+f"((d)[1]), "+f"((d)[2]), "+f"((d)[3])                \
        : "r"((a)[0]), "r"((a)[1]), "r"((a)[2]), "r"((a)[3]), "r"(b0), "r"(b1))

#define SWZ(o) ((o) ^ ((((uint32_t)(o)) >> 3) & 0x70u))

// bf16 hi/lo split of 4 fp32 -> packed (4 bf16 = 8B each)
__device__ __forceinline__ unsigned pack2(__nv_bfloat16 a, __nv_bfloat16 b) {
    __nv_bfloat162 t = __halves2bfloat162(a, b);
    return *reinterpret_cast<unsigned*>(&t);
}
__device__ __forceinline__ void bf16_split4(float4 v, uint2& hi, uint2& lo) {
    __nv_bfloat16 h0 = __float2bfloat16(v.x), h1 = __float2bfloat16(v.y);
    __nv_bfloat16 h2 = __float2bfloat16(v.z), h3 = __float2bfloat16(v.w);
    __nv_bfloat16 l0 = __float2bfloat16(v.x - __bfloat162float(h0));
    __nv_bfloat16 l1 = __float2bfloat16(v.y - __bfloat162float(h1));
    __nv_bfloat16 l2 = __float2bfloat16(v.z - __bfloat162float(h2));
    __nv_bfloat16 l3 = __float2bfloat16(v.w - __bfloat162float(h3));
    hi.x = pack2(h0, h1); hi.y = pack2(h2, h3);
    lo.x = pack2(l0, l1); lo.y = pack2(l2, l3);
}

// SMEM layouts (dynamic):
// GEMM1: A_hi[0,16K) A_lo[16K,32K) then 4 B chunks of 32K (hi 16K + lo 16K)
#define G1_AH   0
#define G1_AL   16384
#define G1_B    32768
#define G1_BSTR 32768
#define G1_SMEM (32768 + 4 * 32768)     // 163840
// GEMM2: A_hi/A_lo 32K, then 2 B chunks of 16K (hi 8K + lo 8K)
#define G2_AH   0
#define G2_AL   16384
#define G2_B    32768
#define G2_BSTR 16384
#define G2_SMEM (32768 + 2 * 16384)     // 65536

// ---------------- degree / CSR build ----------------
__global__ void k_init() {
    int i = blockIdx.x * blockDim.x + threadIdx.x;
    if (i < NN) g_deg[i] = 1;              // self loop
    if (i < 2 * HID)  g_stats1[i] = 0.f;
    if (i < 2 * OUTC) g_stats2[i] = 0.f;
}

__global__ void k_count(const int* __restrict__ dst) {
    int e = blockIdx.x * blockDim.x + threadIdx.x;
    if (e < NE) atomicAdd(&g_deg[dst[e]], 1);
}

__global__ void k_dinv() {
    int i = blockIdx.x * blockDim.x + threadIdx.x;
    if (i < NN) g_dinv[i] = rsqrtf((float)g_deg[i]);
}

__global__ void k_scan_a() {
    __shared__ int s[512];
    int t = threadIdx.x;
    int i = blockIdx.x * 512 + t;
    int v = (i < NN) ? (g_deg[i] - 1) : 0;   // CSR counts exclude self loop
    s[t] = v;
    __syncthreads();
    #pragma unroll
    for (int off = 1; off < 512; off <<= 1) {
        int x = 0;
        if (t >= off) x = s[t - off];
        __syncthreads();
        s[t] += x;
        __syncthreads();
    }
    if (i < NN) g_rowstart[i] = s[t] - v;    // exclusive within block
    if (t == 511) g_blocksums[blockIdx.x] = s[511];
}

__global__ void k_scan_b() {
    __shared__ int s[256];
    int t = threadIdx.x;
    int v = (t < NSB) ? g_blocksums[t] : 0;
    s[t] = v;
    __syncthreads();
    #pragma unroll
    for (int off = 1; off < 256; off <<= 1) {
        int x = 0;
        if (t >= off) x = s[t - off];
        __syncthreads();
        s[t] += x;
        __syncthreads();
    }
    if (t < NSB) g_blockoffs[t] = s[t] - v;
}

__global__ void k_scan_c() {
    int t = threadIdx.x;
    int b = blockIdx.x;
    int i = b * 512 + t;
    if (i < NN) {
        int r = g_rowstart[i] + g_blockoffs[b];
        g_rowstart[i] = r;
        g_cursor[i] = r;
    }
    if (i == 0) g_rowstart[NN] = NE;
}

__global__ void k_fill(const int* __restrict__ src, const int* __restrict__ dst) {
    int e = blockIdx.x * blockDim.x + threadIdx.x;
    if (e >= NE) return;
    int d = dst[e];
    int p = atomicAdd(&g_cursor[d], 1);
    g_col[p] = src[e];
}

// ================= GEMM1 (mma.sync bf16 split): g_h1 = dinv * (X @ W1) ========
// BM=128, BN=128, BK=64 x 4 chunks. 8 warps: 4(M) x 2(N), warp tile 32x64.
__global__ __launch_bounds__(256, 1) void k_gemm1_mma(const float* __restrict__ X,
                                                      const float* __restrict__ W) {
    extern __shared__ char smem[];
    uint32_t sb = smem_u32(smem);
    const int tid = threadIdx.x, wid = tid >> 5, lane = tid & 31;
    const int bm = blockIdx.x * 128;
    const int wm = wid & 3, wn = wid >> 2;

    float acc[2][8][4];
    #pragma unroll
    for (int i = 0; i < 2; i++)
        #pragma unroll
        for (int j = 0; j < 8; j++)
            #pragma unroll
            for (int k = 0; k < 4; k++) acc[i][j][k] = 0.f;

    // ldmatrix per-lane base addresses (row*128 folded in; swizzle xor separate)
    const int arow = wm * 32 + (lane & 15);
    const uint32_t a_base = sb + G1_AH + arow * 128;
    const uint32_t a_xor  = (uint32_t)((arow & 7) * 16);
    const uint32_t a_kb   = (uint32_t)((lane >> 4) << 4);      // 0 | 16

    const int brow = wn * 64 + (lane & 7) + ((lane >> 4) << 3);
    const uint32_t b_rowoff = (uint32_t)(brow * 128);
    const uint32_t b_xor  = (uint32_t)((brow & 7) * 16);
    const uint32_t b_kb   = (uint32_t)(((lane >> 3) & 1) << 4); // 0 | 16

    // ---- stage ALL B chunks once: B[n][k] = W1[k][n], hi/lo split, swizzled
    #pragma unroll
    for (int it = 0; it < 32; it++) {
        int id  = tid + it * 256;            // 0..8191 quads
        int c   = id >> 11;
        int rem = id & 2047;
        int n   = rem & 127;
        int kq  = (rem >> 7) * 4;            // 0..60
        const float* wp = W + (size_t)(c * 64 + kq) * HID + n;
        float4 v = make_float4(wp[0], wp[HID], wp[2 * HID], wp[3 * HID]);
        uint2 h, l; bf16_split4(v, h, l);
        uint32_t off = SWZ((uint32_t)(n * 128 + kq * 2));
        *(uint2*)(smem + G1_B + c * G1_BSTR + off)         = h;
        *(uint2*)(smem + G1_B + c * G1_BSTR + 16384 + off) = l;
    }

    for (int c = 0; c < 4; c++) {
        // ---- stage A chunk (hi/lo), coalesced global, ~conflict-free smem
        #pragma unroll
        for (int it = 0; it < 8; it++) {
            int id  = tid + it * 256;        // 0..2047 quads
            int row = id >> 4;
            int kq  = (id & 15) * 4;
            int gr  = bm + row;
            float4 v = make_float4(0.f, 0.f, 0.f, 0.f);
            if (gr < NN) v = *(const float4*)(X + (size_t)gr * FEAT + c * 64 + kq);
            uint2 h, l; bf16_split4(v, h, l);
            uint32_t off = SWZ((uint32_t)(row * 128 + kq * 2));
            *(uint2*)(smem + G1_AH + off) = h;
            *(uint2*)(smem + G1_AL + off) = l;
        }
        __syncthreads();

        const uint32_t bb = sb + G1_B + c * G1_BSTR + b_rowoff;
        #pragma unroll
        for (int ks = 0; ks < 4; ks++) {
            uint32_t ah[2][4], al[2][4], bh[4][4], bl[4][4];
            uint32_t ka = ((uint32_t)(ks * 32) + a_kb) ^ a_xor;
            LDSM4(ah[0], a_base + ka);
            LDSM4(ah[1], a_base + 2048 + ka);
            LDSM4(al[0], a_base + 16384 + ka);
            LDSM4(al[1], a_base + 16384 + 2048 + ka);
            uint32_t kb = ((uint32_t)(ks * 32) + b_kb) ^ b_xor;
            #pragma unroll
            for (int p = 0; p < 4; p++) {
                LDSM4(bh[p], bb + p * 2048 + kb);
                LDSM4(bl[p], bb + 16384 + p * 2048 + kb);
            }
            #pragma unroll
            for (int mt = 0; mt < 2; mt++)
                #pragma unroll
                for (int nt = 0; nt < 8; nt++) {
                    uint32_t b0h = bh[nt >> 1][(nt & 1) * 2], b1h = bh[nt >> 1][(nt & 1) * 2 + 1];
                    uint32_t b0l = bl[nt >> 1][(nt & 1) * 2], b1l = bl[nt >> 1][(nt & 1) * 2 + 1];
                    MMAB(acc[mt][nt], ah[mt], b0h, b1h);
                    MMAB(acc[mt][nt], ah[mt], b0l, b1l);
                    MMAB(acc[mt][nt], al[mt], b0h, b1h);
                }
        }
        __syncthreads();
    }

    // ---- epilogue: dinv prescale, write g_h1
    #pragma unroll
    for (int mt = 0; mt < 2; mt++) {
        int r0 = bm + wm * 32 + mt * 16 + (lane >> 2);
        int r1 = r0 + 8;
        float dv0 = (r0 < NN) ? g_dinv[r0] : 0.f;
        float dv1 = (r1 < NN) ? g_dinv[r1] : 0.f;
        #pragma unroll
        for (int nt = 0; nt < 8; nt++) {
            int col = wn * 64 + nt * 8 + (lane & 3) * 2;
            if (r0 < NN) {
                float2 q; q.x = acc[mt][nt][0] * dv0; q.y = acc[mt][nt][1] * dv0;
                *(float2*)(g_h1 + (size_t)r0 * HID + col) = q;
            }
            if (r1 < NN) {
                float2 q; q.x = acc[mt][nt][2] * dv1; q.y = acc[mt][nt][3] * dv1;
                *(float2*)(g_h1 + (size_t)r1 * HID + col) = q;
            }
        }
    }
}

// ---------------- propagate layer1: warp per node, float4 lanes ----------------
__global__ void k_prop128(const float* __restrict__ bias) {
    int gt = blockIdx.x * blockDim.x + threadIdx.x;
    int v = gt >> 5;
    if (v >= NN) return;
    int lane = gt & 31;
    const float4* hp = (const float4*)g_h1;
    float4 acc = hp[(size_t)v * 32 + lane];        // self loop (prescaled)
    int beg = g_rowstart[v], end = g_rowstart[v + 1];
    for (int j = beg; j < end; j++) {
        int s = __ldg(&g_col[j]);
        float4 x = hp[(size_t)s * 32 + lane];
        acc.x += x.x; acc.y += x.y; acc.z += x.z; acc.w += x.w;
    }
    float dv = g_dinv[v];
    float4 b = ((const float4*)bias)[lane];
    float4 o;
    o.x = fmaf(acc.x, dv, b.x); o.y = fmaf(acc.y, dv, b.y);
    o.z = fmaf(acc.z, dv, b.z); o.w = fmaf(acc.w, dv, b.w);
    ((float4*)g_p1)[(size_t)v * 32 + lane] = o;
}

// ---------------- BN stats over p1 (sum, sumsq per channel) ----------------
__global__ void k_stats1() {
    const int C = HID, RPB = 256 / C;      // 2 rows per block-iter
    int c = threadIdx.x % C;
    int rsub = threadIdx.x / C;
    float s = 0.f, ss = 0.f;
    for (int r = blockIdx.x * RPB + rsub; r < NN; r += gridDim.x * RPB) {
        float v = g_p1[(size_t)r * C + c];
        s += v; ss += v * v;
    }
    __shared__ float sh[256], sh2[256];
    sh[threadIdx.x] = s; sh2[threadIdx.x] = ss;
    __syncthreads();
    if (rsub == 0) {
        #pragma unroll
        for (int k = 1; k < RPB; k++) { s += sh[k * C + c]; ss += sh2[k * C + c]; }
        atomicAdd(&g_stats1[c], s);
        atomicAdd(&g_stats1[C + c], ss);
    }
}

// ================= GEMM2: g_h2 = dinv * (relu(BN1(p1)) @ W2) ==================
// BM=128, BN=64, BK=64 x 2 chunks. 8 warps: 4(M) x 2(N), warp tile 32x32.
__global__ __launch_bounds__(256, 1) void k_gemm2_mma(const float* __restrict__ W2,
                                                      const float* __restrict__ gamma1,
                                                      const float* __restrict__ beta1) {
    extern __shared__ char smem[];
    __shared__ float bnA[HID], bnB[HID];
    uint32_t sb = smem_u32(smem);
    const int tid = threadIdx.x, wid = tid >> 5, lane = tid & 31;
    const int bm = blockIdx.x * 128;
    const int wm = wid & 3, wn = wid >> 2;

    if (tid < HID) {
        float s  = g_stats1[tid], ss = g_stats1[HID + tid];
        float mu = s * (1.0f / NN);
        float var = ss * (1.0f / NN) - mu * mu;
        float rs = rsqrtf(var + EPSV);
        float ga = gamma1[tid];
        bnA[tid] = rs * ga;
        bnB[tid] = beta1[tid] - mu * rs * ga;
    }

    float acc[2][4][4];
    #pragma unroll
    for (int i = 0; i < 2; i++)
        #pragma unroll
        for (int j = 0; j < 4; j++)
            #pragma unroll
            for (int k = 0; k < 4; k++) acc[i][j][k] = 0.f;

    const int arow = wm * 32 + (lane & 15);
    const uint32_t a_base = sb + G2_AH + arow * 128;
    const uint32_t a_xor  = (uint32_t)((arow & 7) * 16);
    const uint32_t a_kb   = (uint32_t)((lane >> 4) << 4);

    const int brow = wn * 32 + (lane & 7) + ((lane >> 4) << 3);
    const uint32_t b_rowoff = (uint32_t)(brow * 128);
    const uint32_t b_xor  = (uint32_t)((brow & 7) * 16);
    const uint32_t b_kb   = (uint32_t)(((lane >> 3) & 1) << 4);

    // stage both B chunks: B[n][k] = W2[k][n]
    #pragma unroll
    for (int it = 0; it < 8; it++) {
        int id  = tid + it * 256;           // 0..2047 quads
        int c   = id >> 10;
        int rem = id & 1023;
        int n   = rem & 63;
        int kq  = (rem >> 6) * 4;           // 0..60
        const float* wp = W2 + (size_t)(c * 64 + kq) * OUTC + n;
        float4 v = make_float4(wp[0], wp[OUTC], wp[2 * OUTC], wp[3 * OUTC]);
        uint2 h, l; bf16_split4(v, h, l);
        uint32_t off = SWZ((uint32_t)(n * 128 + kq * 2));
        *(uint2*)(smem + G2_B + c * G2_BSTR + off)        = h;
        *(uint2*)(smem + G2_B + c * G2_BSTR + 8192 + off) = l;
    }
    __syncthreads();   // bn coeffs + B ready

    for (int c = 0; c < 2; c++) {
        #pragma unroll
        for (int it = 0; it < 8; it++) {
            int id  = tid + it * 256;
            int row = id >> 4;
            int kq  = (id & 15) * 4;
            int gr  = bm + row;
            float4 v = make_float4(0.f, 0.f, 0.f, 0.f);
            if (gr < NN) {
                v = *(const float4*)(g_p1 + (size_t)gr * HID + c * 64 + kq);
                int kc = c * 64 + kq;
                v.x = fmaxf(0.f, fmaf(v.x, bnA[kc + 0], bnB[kc + 0]));
                v.y = fmaxf(0.f, fmaf(v.y, bnA[kc + 1], bnB[kc + 1]));
                v.z = fmaxf(0.f, fmaf(v.z, bnA[kc + 2], bnB[kc + 2]));
                v.w = fmaxf(0.f, fmaf(v.w, bnA[kc + 3], bnB[kc + 3]));
            }
            uint2 h, l; bf16_split4(v, h, l);
            uint32_t off = SWZ((uint32_t)(row * 128 + kq * 2));
            *(uint2*)(smem + G2_AH + off) = h;
            *(uint2*)(smem + G2_AL + off) = l;
        }
        __syncthreads();

        const uint32_t bb = sb + G2_B + c * G2_BSTR + b_rowoff;
        #pragma unroll
        for (int ks = 0; ks < 4; ks++) {
            uint32_t ah[2][4], al[2][4], bh[2][4], bl[2][4];
            uint32_t ka = ((uint32_t)(ks * 32) + a_kb) ^ a_xor;
            LDSM4(ah[0], a_base + ka);
            LDSM4(ah[1], a_base + 2048 + ka);
            LDSM4(al[0], a_base + 16384 + ka);
            LDSM4(al[1], a_base + 16384 + 2048 + ka);
            uint32_t kb = ((uint32_t)(ks * 32) + b_kb) ^ b_xor;
            #pragma unroll
            for (int p = 0; p < 2; p++) {
                LDSM4(bh[p], bb + p * 2048 + kb);
                LDSM4(bl[p], bb + 8192 + p * 2048 + kb);
            }
            #pragma unroll
            for (int mt = 0; mt < 2; mt++)
                #pragma unroll
                for (int nt = 0; nt < 4; nt++) {
                    uint32_t b0h = bh[nt >> 1][(nt & 1) * 2], b1h = bh[nt >> 1][(nt & 1) * 2 + 1];
                    uint32_t b0l = bl[nt >> 1][(nt & 1) * 2], b1l = bl[nt >> 1][(nt & 1) * 2 + 1];
                    MMAB(acc[mt][nt], ah[mt], b0h, b1h);
                    MMAB(acc[mt][nt], ah[mt], b0l, b1l);
                    MMAB(acc[mt][nt], al[mt], b0h, b1h);
                }
        }
        __syncthreads();
    }

    #pragma unroll
    for (int mt = 0; mt < 2; mt++) {
        int r0 = bm + wm * 32 + mt * 16 + (lane >> 2);
        int r1 = r0 + 8;
        float dv0 = (r0 < NN) ? g_dinv[r0] : 0.f;
        float dv1 = (r1 < NN) ? g_dinv[r1] : 0.f;
        #pragma unroll
        for (int nt = 0; nt < 4; nt++) {
            int col = wn * 32 + nt * 8 + (lane & 3) * 2;
            if (r0 < NN) {
                float2 q; q.x = acc[mt][nt][0] * dv0; q.y = acc[mt][nt][1] * dv0;
                *(float2*)(g_h2 + (size_t)r0 * OUTC + col) = q;
            }
            if (r1 < NN) {
                float2 q; q.x = acc[mt][nt][2] * dv1; q.y = acc[mt][nt][3] * dv1;
                *(float2*)(g_h2 + (size_t)r1 * OUTC + col) = q;
            }
        }
    }
}

// ---------------- propagate layer2: warp per node, float2 lanes ----------------
__global__ void k_prop64(const float* __restrict__ bias) {
    int gt = blockIdx.x * blockDim.x + threadIdx.x;
    int v = gt >> 5;
    if (v >= NN) return;
    int lane = gt & 31;
    const float2* hp = (const float2*)g_h2;
    float2 acc = hp[(size_t)v * 32 + lane];
    int beg = g_rowstart[v], end = g_rowstart[v + 1];
    for (int j = beg; j < end; j++) {
        int s = __ldg(&g_col[j]);
        float2 x = hp[(size_t)s * 32 + lane];
        acc.x += x.x; acc.y += x.y;
    }
    float dv = g_dinv[v];
    float2 b = ((const float2*)bias)[lane];
    float2 o;
    o.x = fmaf(acc.x, dv, b.x); o.y = fmaf(acc.y, dv, b.y);
    ((float2*)g_p2)[(size_t)v * 32 + lane] = o;
}

__global__ void k_stats2() {
    const int C = OUTC, RPB = 256 / C;     // 4 rows per block-iter
    int c = threadIdx.x % C;
    int rsub = threadIdx.x / C;
    float s = 0.f, ss = 0.f;
    for (int r = blockIdx.x * RPB + rsub; r < NN; r += gridDim.x * RPB) {
        float v = g_p2[(size_t)r * C + c];
        s += v; ss += v * v;
    }
    __shared__ float sh[256], sh2[256];
    sh[threadIdx.x] = s; sh2[threadIdx.x] = ss;
    __syncthreads();
    if (rsub == 0) {
        #pragma unroll
        for (int k = 1; k < RPB; k++) { s += sh[k * C + c]; ss += sh2[k * C + c]; }
        atomicAdd(&g_stats2[c], s);
        atomicAdd(&g_stats2[C + c], ss);
    }
}

// ---------------- final: gather batch, BN2+relu+log_softmax ----------------
__global__ void k_final(const int* __restrict__ bn,
                        const float* __restrict__ gamma2,
                        const float* __restrict__ beta2,
                        float* __restrict__ out) {
    int gt = blockIdx.x * blockDim.x + threadIdx.x;
    int w = gt >> 5;
    if (w >= NB) return;
    int lane = gt & 31;
    int node = bn[w];
    float2 v = ((const float2*)g_p2)[(size_t)node * 32 + lane];
    int c0 = lane * 2, c1 = c0 + 1;
    float x0, x1;
    {
        float s = g_stats2[c0], ss = g_stats2[OUTC + c0];
        float mu = s * (1.f / NN);
        float var = ss * (1.f / NN) - mu * mu;
        float rs = rsqrtf(var + EPSV);
        x0 = fmaxf(0.f, (v.x - mu) * rs * gamma2[c0] + beta2[c0]);
    }
    {
        float s = g_stats2[c1], ss = g_stats2[OUTC + c1];
        float mu = s * (1.f / NN);
        float var = ss * (1.f / NN) - mu * mu;
        float rs = rsqrtf(var + EPSV);
        x1 = fmaxf(0.f, (v.y - mu) * rs * gamma2[c1] + beta2[c1]);
    }
    float m = fmaxf(x0, x1);
    #pragma unroll
    for (int o = 16; o; o >>= 1) m = fmaxf(m, __shfl_xor_sync(0xffffffffu, m, o));
    float e = expf(x0 - m) + expf(x1 - m);
    #pragma unroll
    for (int o = 16; o; o >>= 1) e += __shfl_xor_sync(0xffffffffu, e, o);
    float l = m + logf(e);
    float2 r;
    r.x = x0 - l; r.y = x1 - l;
    ((float2*)out)[(size_t)w * 32 + lane] = r;
}

// ---------------- launch ----------------
extern "C" void kernel_launch(void* const* d_in, const int* in_sizes, int n_in,
                              void* d_out, int out_size) {
    const float* features = (const float*)d_in[0];
    const int*   ei       = (const int*)d_in[1];
    const int*   batch    = (const int*)d_in[2];
    const float* W1       = (const float*)d_in[3];
    const float* b1       = (const float*)d_in[4];
    const float* gamma1   = (const float*)d_in[5];
    const float* beta1    = (const float*)d_in[6];
    const float* W2       = (const float*)d_in[7];
    const float* b2       = (const float*)d_in[8];
    const float* gamma2   = (const float*)d_in[9];
    const float* beta2    = (const float*)d_in[10];
    const int* src = ei;
    const int* dst = ei + NE;
    float* out = (float*)d_out;

    cudaFuncSetAttribute(k_gemm1_mma, cudaFuncAttributeMaxDynamicSharedMemorySize, G1_SMEM);
    cudaFuncSetAttribute(k_gemm2_mma, cudaFuncAttributeMaxDynamicSharedMemorySize, G2_SMEM);

    k_init  <<<(NN + 255) / 256, 256>>>();
    k_count <<<(NE + 255) / 256, 256>>>(dst);
    k_dinv  <<<(NN + 255) / 256, 256>>>();
    k_scan_a<<<NSB, 512>>>();
    k_scan_b<<<1, 256>>>();
    k_scan_c<<<NSB, 512>>>();
    k_fill  <<<(NE + 255) / 256, 256>>>(src, dst);

    k_gemm1_mma<<<(NN + 127) / 128, 256, G1_SMEM>>>(features, W1);
    k_prop128  <<<(NN * 32) / 256, 256>>>(b1);
    k_stats1   <<<256, 256>>>();

    k_gemm2_mma<<<(NN + 127) / 128, 256, G2_SMEM>>>(W2, gamma1, beta1);
    k_prop64   <<<(NN * 32) / 256, 256>>>(b2);
    k_stats2   <<<256, 256>>>();

    k_final    <<<(NB * 32) / 256, 256>>>(batch, gamma2, beta2, out);
}

// round 13
// speedup vs baseline: 1.4654x; 1.1114x over previous
#include <cuda_runtime.h>
#include <cuda_bf16.h>
#include <cstdint>

#define NN   100000
#define NE   1600000
#define FEAT 256
#define HID  128
#define OUTC 64
#define NB   10000
#define EPSV 1e-5f

#define NSB  ((NN + 511) / 512)   // 196 scan blocks
#define PB   2048                 // propagate grid blocks

// ---------------- device scratch (static, allocation-free) ----------------
__device__ int   g_deg[NN];
__device__ float g_dinv[NN];
__device__ int   g_rowstart[NN + 1];
__device__ int   g_cursor[NN];
__device__ int   g_col[NE];
__device__ int   g_blocksums[NSB];
__device__ int   g_blockoffs[NSB];
__device__ float g_h1[(size_t)NN * HID];   // dinv-prescaled X@W1
__device__ float g_p1[(size_t)NN * HID];   // propagated layer1 (pre-BN)
__device__ float g_h2[(size_t)NN * OUTC];
__device__ float g_p2[(size_t)NN * OUTC];
__device__ float g_stats1[2 * HID];        // [sum | sumsq]
__device__ float g_stats2[2 * OUTC];

// ================= warp-MMA helpers (arch-neutral: ldmatrix + mma.sync) ======
__device__ __forceinline__ uint32_t smem_u32(const void* p) {
    uint32_t a;
    asm("{ .reg .u64 t; cvta.to.shared.u64 t, %1; cvt.u32.u64 %0, t; }" : "=r"(a) : "l"(p));
    return a;
}

#define LDSM4(r, addr)                                                          \
    asm volatile("ldmatrix.sync.aligned.m8n8.x4.shared.b16 {%0,%1,%2,%3}, [%4];"\
        : "=r"((r)[0]), "=r"((r)[1]), "=r"((r)[2]), "=r"((r)[3]) : "r"(addr))

#define MMAB(d, a, b0, b1)                                                      \
    asm volatile("mma.sync.aligned.m16n8k16.row.col.f32.bf16.bf16.f32 "         \
        "{%0,%1,%2,%3},{%4,%5,%6,%7},{%8,%9},{%0,%1,%2,%3};"                    \
        : "+f"((d)[0]), "+f"((d)[1]), "+f"((d)[2]), "+f"((d)[3])                \
        : "r"((a)[0]), "r"((a)[1]), "r"((a)[2]), "r"((a)[3]), "r"(b0), "r"(b1))

#define SWZ(o) ((o) ^ ((((uint32_t)(o)) >> 3) & 0x70u))

// bf16 hi/lo split of 4 fp32 -> packed (4 bf16 = 8B each)
__device__ __forceinline__ unsigned pack2(__nv_bfloat16 a, __nv_bfloat16 b) {
    __nv_bfloat162 t = __halves2bfloat162(a, b);
    return *reinterpret_cast<unsigned*>(&t);
}
__device__ __forceinline__ void bf16_split4(float4 v, uint2& hi, uint2& lo) {
    __nv_bfloat16 h0 = __float2bfloat16(v.x), h1 = __float2bfloat16(v.y);
    __nv_bfloat16 h2 = __float2bfloat16(v.z), h3 = __float2bfloat16(v.w);
    __nv_bfloat16 l0 = __float2bfloat16(v.x - __bfloat162float(h0));
    __nv_bfloat16 l1 = __float2bfloat16(v.y - __bfloat162float(h1));
    __nv_bfloat16 l2 = __float2bfloat16(v.z - __bfloat162float(h2));
    __nv_bfloat16 l3 = __float2bfloat16(v.w - __bfloat162float(h3));
    hi.x = pack2(h0, h1); hi.y = pack2(h2, h3);
    lo.x = pack2(l0, l1); lo.y = pack2(l2, l3);
}

// SMEM layouts (dynamic):
// GEMM1: B 4 chunks x 32K (hi16K+lo16K) at 0; A double-buffered 2 x 32K at 128K
#define G1_B    0
#define G1_BSTR 32768
#define G1_A    131072
#define G1_ASTR 32768
#define G1_SMEM (131072 + 2 * 32768)    // 196608 (192KB)
// GEMM2: B 2 chunks x 16K (hi8K+lo8K) at 0; A double-buffered 2 x 32K at 32K
#define G2_B    0
#define G2_BSTR 16384
#define G2_A    32768
#define G2_ASTR 32768
#define G2_SMEM (32768 + 2 * 32768)     // 98304 (96KB)

// ---------------- degree / CSR build ----------------
__global__ void k_init() {
    int i = blockIdx.x * blockDim.x + threadIdx.x;
    if (i < NN) g_deg[i] = 1;              // self loop
    if (i < 2 * HID)  g_stats1[i] = 0.f;
    if (i < 2 * OUTC) g_stats2[i] = 0.f;
}

__global__ void k_count(const int* __restrict__ dst) {
    int e = blockIdx.x * blockDim.x + threadIdx.x;
    if (e < NE) atomicAdd(&g_deg[dst[e]], 1);
}

__global__ void k_scan_a() {
    __shared__ int s[512];
    int t = threadIdx.x;
    int i = blockIdx.x * 512 + t;
    int v = 0;
    if (i < NN) {
        int d = g_deg[i];
        v = d - 1;                         // CSR counts exclude self loop
        g_dinv[i] = rsqrtf((float)d);      // fused dinv
    }
    s[t] = v;
    __syncthreads();
    #pragma unroll
    for (int off = 1; off < 512; off <<= 1) {
        int x = 0;
        if (t >= off) x = s[t - off];
        __syncthreads();
        s[t] += x;
        __syncthreads();
    }
    if (i < NN) g_rowstart[i] = s[t] - v;    // exclusive within block
    if (t == 511) g_blocksums[blockIdx.x] = s[511];
}

__global__ void k_scan_b() {
    __shared__ int s[256];
    int t = threadIdx.x;
    int v = (t < NSB) ? g_blocksums[t] : 0;
    s[t] = v;
    __syncthreads();
    #pragma unroll
    for (int off = 1; off < 256; off <<= 1) {
        int x = 0;
        if (t >= off) x = s[t - off];
        __syncthreads();
        s[t] += x;
        __syncthreads();
    }
    if (t < NSB) g_blockoffs[t] = s[t] - v;
}

__global__ void k_scan_c() {
    int t = threadIdx.x;
    int b = blockIdx.x;
    int i = b * 512 + t;
    if (i < NN) {
        int r = g_rowstart[i] + g_blockoffs[b];
        g_rowstart[i] = r;
        g_cursor[i] = r;
    }
    if (i == 0) g_rowstart[NN] = NE;
}

__global__ void k_fill(const int* __restrict__ src, const int* __restrict__ dst) {
    int e = blockIdx.x * blockDim.x + threadIdx.x;
    if (e >= NE) return;
    int d = dst[e];
    int p = atomicAdd(&g_cursor[d], 1);
    g_col[p] = src[e];
}

// ================= GEMM1 (mma.sync bf16 split): g_h1 = dinv * (X @ W1) ========
// BM=128, BN=128, BK=64 x 4 chunks. 8 warps: 4(M) x 2(N), warp tile 32x64.
// A staging double-buffered: LDG chunk c+1 issued before computing chunk c.
__global__ __launch_bounds__(256, 1) void k_gemm1_mma(const float* __restrict__ X,
                                                      const float* __restrict__ W) {
    extern __shared__ char smem[];
    uint32_t sb = smem_u32(smem);
    const int tid = threadIdx.x, wid = tid >> 5, lane = tid & 31;
    const int bm = blockIdx.x * 128;
    const int wm = wid & 3, wn = wid >> 2;

    float acc[2][8][4];
    #pragma unroll
    for (int i = 0; i < 2; i++)
        #pragma unroll
        for (int j = 0; j < 8; j++)
            #pragma unroll
            for (int k = 0; k < 4; k++) acc[i][j][k] = 0.f;

    // ldmatrix per-lane addresses
    const int arow = wm * 32 + (lane & 15);
    const uint32_t a_off  = (uint32_t)(arow * 128);
    const uint32_t a_xor  = (uint32_t)((arow & 7) * 16);
    const uint32_t a_kb   = (uint32_t)((lane >> 4) << 4);      // 0 | 16

    const int brow = wn * 64 + (lane & 7) + ((lane >> 4) << 3);
    const uint32_t b_rowoff = (uint32_t)(brow * 128);
    const uint32_t b_xor  = (uint32_t)((brow & 7) * 16);
    const uint32_t b_kb   = (uint32_t)(((lane >> 3) & 1) << 4); // 0 | 16

    // per-thread A staging coords
    const int s_row = tid >> 4;             // 0..15 base rows (x8 iters -> 128)
    const int s_kq  = (tid & 15) * 4;

    // ---- stage ALL B chunks once: B[n][k] = W1[k][n], hi/lo split, swizzled
    #pragma unroll
    for (int it = 0; it < 32; it++) {
        int id  = tid + it * 256;            // 0..8191 quads
        int c   = id >> 11;
        int rem = id & 2047;
        int n   = rem & 127;
        int kq  = (rem >> 7) * 4;            // 0..60
        const float* wp = W + (size_t)(c * 64 + kq) * HID + n;
        float4 v = make_float4(wp[0], wp[HID], wp[2 * HID], wp[3 * HID]);
        uint2 h, l; bf16_split4(v, h, l);
        uint32_t off = SWZ((uint32_t)(n * 128 + kq * 2));
        *(uint2*)(smem + G1_B + c * G1_BSTR + off)         = h;
        *(uint2*)(smem + G1_B + c * G1_BSTR + 16384 + off) = l;
    }

    // ---- prefetch chunk 0 into regs, stage to buffer 0
    float4 v[8];
    #pragma unroll
    for (int it = 0; it < 8; it++) {
        int row = s_row + it * 16;
        int gr  = bm + row;
        v[it] = (gr < NN) ? *(const float4*)(X + (size_t)gr * FEAT + s_kq)
                          : make_float4(0.f, 0.f, 0.f, 0.f);
    }
    #pragma unroll
    for (int it = 0; it < 8; it++) {
        int row = s_row + it * 16;
        uint2 h, l; bf16_split4(v[it], h, l);
        uint32_t off = SWZ((uint32_t)(row * 128 + s_kq * 2));
        *(uint2*)(smem + G1_A + off)         = h;
        *(uint2*)(smem + G1_A + 16384 + off) = l;
    }
    __syncthreads();

    for (int c = 0; c < 4; c++) {
        // issue prefetch of next chunk (hidden behind MMA compute)
        if (c < 3) {
            #pragma unroll
            for (int it = 0; it < 8; it++) {
                int row = s_row + it * 16;
                int gr  = bm + row;
                v[it] = (gr < NN) ? *(const float4*)(X + (size_t)gr * FEAT + (c + 1) * 64 + s_kq)
                                  : make_float4(0.f, 0.f, 0.f, 0.f);
            }
        }

        const uint32_t abuf = sb + G1_A + (c & 1) * G1_ASTR;
        const uint32_t a_base = abuf + a_off;
        const uint32_t bb = sb + G1_B + c * G1_BSTR + b_rowoff;
        #pragma unroll
        for (int ks = 0; ks < 4; ks++) {
            uint32_t ah[2][4], al[2][4], bh[4][4], bl[4][4];
            uint32_t ka = ((uint32_t)(ks * 32) + a_kb) ^ a_xor;
            LDSM4(ah[0], a_base + ka);
            LDSM4(ah[1], a_base + 2048 + ka);
            LDSM4(al[0], a_base + 16384 + ka);
            LDSM4(al[1], a_base + 16384 + 2048 + ka);
            uint32_t kb = ((uint32_t)(ks * 32) + b_kb) ^ b_xor;
            #pragma unroll
            for (int p = 0; p < 4; p++) {
                LDSM4(bh[p], bb + p * 2048 + kb);
                LDSM4(bl[p], bb + 16384 + p * 2048 + kb);
            }
            #pragma unroll
            for (int mt = 0; mt < 2; mt++)
                #pragma unroll
                for (int nt = 0; nt < 8; nt++) {
                    uint32_t b0h = bh[nt >> 1][(nt & 1) * 2], b1h = bh[nt >> 1][(nt & 1) * 2 + 1];
                    uint32_t b0l = bl[nt >> 1][(nt & 1) * 2], b1l = bl[nt >> 1][(nt & 1) * 2 + 1];
                    MMAB(acc[mt][nt], ah[mt], b0h, b1h);
                    MMAB(acc[mt][nt], ah[mt], b0l, b1l);
                    MMAB(acc[mt][nt], al[mt], b0h, b1h);
                }
        }

        // store prefetched chunk into the other buffer (safe: its readers
        // finished before the previous __syncthreads)
        if (c < 3) {
            char* dst = smem + G1_A + ((c + 1) & 1) * G1_ASTR;
            #pragma unroll
            for (int it = 0; it < 8; it++) {
                int row = s_row + it * 16;
                uint2 h, l; bf16_split4(v[it], h, l);
                uint32_t off = SWZ((uint32_t)(row * 128 + s_kq * 2));
                *(uint2*)(dst + off)         = h;
                *(uint2*)(dst + 16384 + off) = l;
            }
        }
        __syncthreads();
    }

    // ---- epilogue: dinv prescale, write g_h1
    #pragma unroll
    for (int mt = 0; mt < 2; mt++) {
        int r0 = bm + wm * 32 + mt * 16 + (lane >> 2);
        int r1 = r0 + 8;
        float dv0 = (r0 < NN) ? g_dinv[r0] : 0.f;
        float dv1 = (r1 < NN) ? g_dinv[r1] : 0.f;
        #pragma unroll
        for (int nt = 0; nt < 8; nt++) {
            int col = wn * 64 + nt * 8 + (lane & 3) * 2;
            if (r0 < NN) {
                float2 q; q.x = acc[mt][nt][0] * dv0; q.y = acc[mt][nt][1] * dv0;
                *(float2*)(g_h1 + (size_t)r0 * HID + col) = q;
            }
            if (r1 < NN) {
                float2 q; q.x = acc[mt][nt][2] * dv1; q.y = acc[mt][nt][3] * dv1;
                *(float2*)(g_h1 + (size_t)r1 * HID + col) = q;
            }
        }
    }
}

// ------- propagate layer1 (+fused BN stats): warp/node, grid-stride ---------
__global__ __launch_bounds__(256) void k_prop128(const float* __restrict__ bias) {
    int tid = threadIdx.x, lane = tid & 31, wid = tid >> 5;
    const float4* hp = (const float4*)g_h1;
    float4 b = ((const float4*)bias)[lane];
    float4 s1 = make_float4(0.f, 0.f, 0.f, 0.f);
    float4 s2 = make_float4(0.f, 0.f, 0.f, 0.f);

    for (int vtx = blockIdx.x * 8 + wid; vtx < NN; vtx += PB * 8) {
        float4 acc0 = hp[(size_t)vtx * 32 + lane];        // self loop (prescaled)
        float4 acc1 = make_float4(0.f, 0.f, 0.f, 0.f);
        int beg = g_rowstart[vtx], end = g_rowstart[vtx + 1];
        int j = beg;
        for (; j + 2 <= end; j += 2) {
            int sa = __ldg(&g_col[j]), sbv = __ldg(&g_col[j + 1]);
            float4 x0 = hp[(size_t)sa * 32 + lane];
            float4 x1 = hp[(size_t)sbv * 32 + lane];
            acc0.x += x0.x; acc0.y += x0.y; acc0.z += x0.z; acc0.w += x0.w;
            acc1.x += x1.x; acc1.y += x1.y; acc1.z += x1.z; acc1.w += x1.w;
        }
        if (j < end) {
            int sa = __ldg(&g_col[j]);
            float4 x = hp[(size_t)sa * 32 + lane];
            acc0.x += x.x; acc0.y += x.y; acc0.z += x.z; acc0.w += x.w;
        }
        float dv = g_dinv[vtx];
        float4 o;
        o.x = fmaf(acc0.x + acc1.x, dv, b.x);
        o.y = fmaf(acc0.y + acc1.y, dv, b.y);
        o.z = fmaf(acc0.z + acc1.z, dv, b.z);
        o.w = fmaf(acc0.w + acc1.w, dv, b.w);
        ((float4*)g_p1)[(size_t)vtx * 32 + lane] = o;
        s1.x += o.x; s1.y += o.y; s1.z += o.z; s1.w += o.w;
        s2.x += o.x * o.x; s2.y += o.y * o.y; s2.z += o.z * o.z; s2.w += o.w * o.w;
    }

    __shared__ float4 sh1[8][32], sh2[8][32];
    sh1[wid][lane] = s1; sh2[wid][lane] = s2;
    __syncthreads();
    if (wid == 0) {
        float4 t1 = sh1[0][lane], t2 = sh2[0][lane];
        #pragma unroll
        for (int w = 1; w < 8; w++) {
            float4 a1 = sh1[w][lane], a2 = sh2[w][lane];
            t1.x += a1.x; t1.y += a1.y; t1.z += a1.z; t1.w += a1.w;
            t2.x += a2.x; t2.y += a2.y; t2.z += a2.z; t2.w += a2.w;
        }
        int c = lane * 4;
        atomicAdd(&g_stats1[c + 0], t1.x);
        atomicAdd(&g_stats1[c + 1], t1.y);
        atomicAdd(&g_stats1[c + 2], t1.z);
        atomicAdd(&g_stats1[c + 3], t1.w);
        atomicAdd(&g_stats1[HID + c + 0], t2.x);
        atomicAdd(&g_stats1[HID + c + 1], t2.y);
        atomicAdd(&g_stats1[HID + c + 2], t2.z);
        atomicAdd(&g_stats1[HID + c + 3], t2.w);
    }
}

// ================= GEMM2: g_h2 = dinv * (relu(BN1(p1)) @ W2) ==================
// BM=128, BN=64, BK=64 x 2 chunks. 8 warps: 4(M) x 2(N), warp tile 32x32.
__global__ __launch_bounds__(256, 1) void k_gemm2_mma(const float* __restrict__ W2,
                                                      const float* __restrict__ gamma1,
                                                      const float* __restrict__ beta1) {
    extern __shared__ char smem[];
    __shared__ float bnA[HID], bnB[HID];
    uint32_t sb = smem_u32(smem);
    const int tid = threadIdx.x, wid = tid >> 5, lane = tid & 31;
    const int bm = blockIdx.x * 128;
    const int wm = wid & 3, wn = wid >> 2;

    if (tid < HID) {
        float s  = g_stats1[tid], ss = g_stats1[HID + tid];
        float mu = s * (1.0f / NN);
        float var = ss * (1.0f / NN) - mu * mu;
        float rs = rsqrtf(var + EPSV);
        float ga = gamma1[tid];
        bnA[tid] = rs * ga;
        bnB[tid] = beta1[tid] - mu * rs * ga;
    }

    float acc[2][4][4];
    #pragma unroll
    for (int i = 0; i < 2; i++)
        #pragma unroll
        for (int j = 0; j < 4; j++)
            #pragma unroll
            for (int k = 0; k < 4; k++) acc[i][j][k] = 0.f;

    const int arow = wm * 32 + (lane & 15);
    const uint32_t a_off  = (uint32_t)(arow * 128);
    const uint32_t a_xor  = (uint32_t)((arow & 7) * 16);
    const uint32_t a_kb   = (uint32_t)((lane >> 4) << 4);

    const int brow = wn * 32 + (lane & 7) + ((lane >> 4) << 3);
    const uint32_t b_rowoff = (uint32_t)(brow * 128);
    const uint32_t b_xor  = (uint32_t)((brow & 7) * 16);
    const uint32_t b_kb   = (uint32_t)(((lane >> 3) & 1) << 4);

    const int s_row = tid >> 4;
    const int s_kq  = (tid & 15) * 4;

    // stage both B chunks: B[n][k] = W2[k][n]
    #pragma unroll
    for (int it = 0; it < 8; it++) {
        int id  = tid + it * 256;           // 0..2047 quads
        int c   = id >> 10;
        int rem = id & 1023;
        int n   = rem & 63;
        int kq  = (rem >> 6) * 4;           // 0..60
        const float* wp = W2 + (size_t)(c * 64 + kq) * OUTC + n;
        float4 v = make_float4(wp[0], wp[OUTC], wp[2 * OUTC], wp[3 * OUTC]);
        uint2 h, l; bf16_split4(v, h, l);
        uint32_t off = SWZ((uint32_t)(n * 128 + kq * 2));
        *(uint2*)(smem + G2_B + c * G2_BSTR + off)        = h;
        *(uint2*)(smem + G2_B + c * G2_BSTR + 8192 + off) = l;
    }
    __syncthreads();   // bn coeffs + B ready

    // prefetch + BN + split chunk 0
    float4 v[8];
    #pragma unroll
    for (int it = 0; it < 8; it++) {
        int row = s_row + it * 16;
        int gr  = bm + row;
        float4 t = make_float4(0.f, 0.f, 0.f, 0.f);
        if (gr < NN) {
            t = *(const float4*)(g_p1 + (size_t)gr * HID + s_kq);
            t.x = fmaxf(0.f, fmaf(t.x, bnA[s_kq + 0], bnB[s_kq + 0]));
            t.y = fmaxf(0.f, fmaf(t.y, bnA[s_kq + 1], bnB[s_kq + 1]));
            t.z = fmaxf(0.f, fmaf(t.z, bnA[s_kq + 2], bnB[s_kq + 2]));
            t.w = fmaxf(0.f, fmaf(t.w, bnA[s_kq + 3], bnB[s_kq + 3]));
        }
        v[it] = t;
    }
    #pragma unroll
    for (int it = 0; it < 8; it++) {
        int row = s_row + it * 16;
        uint2 h, l; bf16_split4(v[it], h, l);
        uint32_t off = SWZ((uint32_t)(row * 128 + s_kq * 2));
        *(uint2*)(smem + G2_A + off)         = h;
        *(uint2*)(smem + G2_A + 16384 + off) = l;
    }
    __syncthreads();

    for (int c = 0; c < 2; c++) {
        if (c < 1) {
            #pragma unroll
            for (int it = 0; it < 8; it++) {
                int row = s_row + it * 16;
                int gr  = bm + row;
                int kc  = 64 + s_kq;
                float4 t = make_float4(0.f, 0.f, 0.f, 0.f);
                if (gr < NN) {
                    t = *(const float4*)(g_p1 + (size_t)gr * HID + kc);
                    t.x = fmaxf(0.f, fmaf(t.x, bnA[kc + 0], bnB[kc + 0]));
                    t.y = fmaxf(0.f, fmaf(t.y, bnA[kc + 1], bnB[kc + 1]));
                    t.z = fmaxf(0.f, fmaf(t.z, bnA[kc + 2], bnB[kc + 2]));
                    t.w = fmaxf(0.f, fmaf(t.w, bnA[kc + 3], bnB[kc + 3]));
                }
                v[it] = t;
            }
        }

        const uint32_t abuf = sb + G2_A + (c & 1) * G2_ASTR;
        const uint32_t a_base = abuf + a_off;
        const uint32_t bb = sb + G2_B + c * G2_BSTR + b_rowoff;
        #pragma unroll
        for (int ks = 0; ks < 4; ks++) {
            uint32_t ah[2][4], al[2][4], bh[2][4], bl[2][4];
            uint32_t ka = ((uint32_t)(ks * 32) + a_kb) ^ a_xor;
            LDSM4(ah[0], a_base + ka);
            LDSM4(ah[1], a_base + 2048 + ka);
            LDSM4(al[0], a_base + 16384 + ka);
            LDSM4(al[1], a_base + 16384 + 2048 + ka);
            uint32_t kb = ((uint32_t)(ks * 32) + b_kb) ^ b_xor;
            #pragma unroll
            for (int p = 0; p < 2; p++) {
                LDSM4(bh[p], bb + p * 2048 + kb);
                LDSM4(bl[p], bb + 8192 + p * 2048 + kb);
            }
            #pragma unroll
            for (int mt = 0; mt < 2; mt++)
                #pragma unroll
                for (int nt = 0; nt < 4; nt++) {
                    uint32_t b0h = bh[nt >> 1][(nt & 1) * 2], b1h = bh[nt >> 1][(nt & 1) * 2 + 1];
                    uint32_t b0l = bl[nt >> 1][(nt & 1) * 2], b1l = bl[nt >> 1][(nt & 1) * 2 + 1];
                    MMAB(acc[mt][nt], ah[mt], b0h, b1h);
                    MMAB(acc[mt][nt], ah[mt], b0l, b1l);
                    MMAB(acc[mt][nt], al[mt], b0h, b1h);
                }
        }

        if (c < 1) {
            char* dst = smem + G2_A + G2_ASTR;
            #pragma unroll
            for (int it = 0; it < 8; it++) {
                int row = s_row + it * 16;
                uint2 h, l; bf16_split4(v[it], h, l);
                uint32_t off = SWZ((uint32_t)(row * 128 + s_kq * 2));
                *(uint2*)(dst + off)         = h;
                *(uint2*)(dst + 16384 + off) = l;
            }
        }
        __syncthreads();
    }

    #pragma unroll
    for (int mt = 0; mt < 2; mt++) {
        int r0 = bm + wm * 32 + mt * 16 + (lane >> 2);
        int r1 = r0 + 8;
        float dv0 = (r0 < NN) ? g_dinv[r0] : 0.f;
        float dv1 = (r1 < NN) ? g_dinv[r1] : 0.f;
        #pragma unroll
        for (int nt = 0; nt < 4; nt++) {
            int col = wn * 32 + nt * 8 + (lane & 3) * 2;
            if (r0 < NN) {
                float2 q; q.x = acc[mt][nt][0] * dv0; q.y = acc[mt][nt][1] * dv0;
                *(float2*)(g_h2 + (size_t)r0 * OUTC + col) = q;
            }
            if (r1 < NN) {
                float2 q; q.x = acc[mt][nt][2] * dv1; q.y = acc[mt][nt][3] * dv1;
                *(float2*)(g_h2 + (size_t)r1 * OUTC + col) = q;
            }
        }
    }
}

// ------- propagate layer2 (+fused BN stats): warp/node, grid-stride ---------
__global__ __launch_bounds__(256) void k_prop64(const float* __restrict__ bias) {
    int tid = threadIdx.x, lane = tid & 31, wid = tid >> 5;
    const float2* hp = (const float2*)g_h2;
    float2 b = ((const float2*)bias)[lane];
    float2 s1 = make_float2(0.f, 0.f), s2 = make_float2(0.f, 0.f);

    for (int vtx = blockIdx.x * 8 + wid; vtx < NN; vtx += PB * 8) {
        float2 acc0 = hp[(size_t)vtx * 32 + lane];
        float2 acc1 = make_float2(0.f, 0.f);
        int beg = g_rowstart[vtx], end = g_rowstart[vtx + 1];
        int j = beg;
        for (; j + 2 <= end; j += 2) {
            int sa = __ldg(&g_col[j]), sbv = __ldg(&g_col[j + 1]);
            float2 x0 = hp[(size_t)sa * 32 + lane];
            float2 x1 = hp[(size_t)sbv * 32 + lane];
            acc0.x += x0.x; acc0.y += x0.y;
            acc1.x += x1.x; acc1.y += x1.y;
        }
        if (j < end) {
            int sa = __ldg(&g_col[j]);
            float2 x = hp[(size_t)sa * 32 + lane];
            acc0.x += x.x; acc0.y += x.y;
        }
        float dv = g_dinv[vtx];
        float2 o;
        o.x = fmaf(acc0.x + acc1.x, dv, b.x);
        o.y = fmaf(acc0.y + acc1.y, dv, b.y);
        ((float2*)g_p2)[(size_t)vtx * 32 + lane] = o;
        s1.x += o.x; s1.y += o.y;
        s2.x += o.x * o.x; s2.y += o.y * o.y;
    }

    __shared__ float2 sh1[8][32], sh2[8][32];
    sh1[wid][lane] = s1; sh2[wid][lane] = s2;
    __syncthreads();
    if (wid == 0) {
        float2 t1 = sh1[0][lane], t2 = sh2[0][lane];
        #pragma unroll
        for (int w = 1; w < 8; w++) {
            float2 a1 = sh1[w][lane], a2 = sh2[w][lane];
            t1.x += a1.x; t1.y += a1.y;
            t2.x += a2.x; t2.y += a2.y;
        }
        int c = lane * 2;
        atomicAdd(&g_stats2[c + 0], t1.x);
        atomicAdd(&g_stats2[c + 1], t1.y);
        atomicAdd(&g_stats2[OUTC + c + 0], t2.x);
        atomicAdd(&g_stats2[OUTC + c + 1], t2.y);
    }
}

// ---------------- final: gather batch, BN2+relu+log_softmax ----------------
__global__ void k_final(const int* __restrict__ bn,
                        const float* __restrict__ gamma2,
                        const float* __restrict__ beta2,
                        float* __restrict__ out) {
    int gt = blockIdx.x * blockDim.x + threadIdx.x;
    int w = gt >> 5;
    if (w >= NB) return;
    int lane = gt & 31;
    int node = bn[w];
    float2 v = ((const float2*)g_p2)[(size_t)node * 32 + lane];
    int c0 = lane * 2, c1 = c0 + 1;
    float x0, x1;
    {
        float s = g_stats2[c0], ss = g_stats2[OUTC + c0];
        float mu = s * (1.f / NN);
        float var = ss * (1.f / NN) - mu * mu;
        float rs = rsqrtf(var + EPSV);
        x0 = fmaxf(0.f, (v.x - mu) * rs * gamma2[c0] + beta2[c0]);
    }
    {
        float s = g_stats2[c1], ss = g_stats2[OUTC + c1];
        float mu = s * (1.f / NN);
        float var = ss * (1.f / NN) - mu * mu;
        float rs = rsqrtf(var + EPSV);
        x1 = fmaxf(0.f, (v.y - mu) * rs * gamma2[c1] + beta2[c1]);
    }
    float m = fmaxf(x0, x1);
    #pragma unroll
    for (int o = 16; o; o >>= 1) m = fmaxf(m, __shfl_xor_sync(0xffffffffu, m, o));
    float e = expf(x0 - m) + expf(x1 - m);
    #pragma unroll
    for (int o = 16; o; o >>= 1) e += __shfl_xor_sync(0xffffffffu, e, o);
    float l = m + logf(e);
    float2 r;
    r.x = x0 - l; r.y = x1 - l;
    ((float2*)out)[(size_t)w * 32 + lane] = r;
}

// ---------------- launch ----------------
extern "C" void kernel_launch(void* const* d_in, const int* in_sizes, int n_in,
                              void* d_out, int out_size) {
    const float* features = (const float*)d_in[0];
    const int*   ei       = (const int*)d_in[1];
    const int*   batch    = (const int*)d_in[2];
    const float* W1       = (const float*)d_in[3];
    const float* b1       = (const float*)d_in[4];
    const float* gamma1   = (const float*)d_in[5];
    const float* beta1    = (const float*)d_in[6];
    const float* W2       = (const float*)d_in[7];
    const float* b2       = (const float*)d_in[8];
    const float* gamma2   = (const float*)d_in[9];
    const float* beta2    = (const float*)d_in[10];
    const int* src = ei;
    const int* dst = ei + NE;
    float* out = (float*)d_out;

    cudaFuncSetAttribute(k_gemm1_mma, cudaFuncAttributeMaxDynamicSharedMemorySize, G1_SMEM);
    cudaFuncSetAttribute(k_gemm2_mma, cudaFuncAttributeMaxDynamicSharedMemorySize, G2_SMEM);

    k_init  <<<(NN + 255) / 256, 256>>>();
    k_count <<<(NE + 255) / 256, 256>>>(dst);
    k_scan_a<<<NSB, 512>>>();
    k_scan_b<<<1, 256>>>();
    k_scan_c<<<NSB, 512>>>();
    k_fill  <<<(NE + 255) / 256, 256>>>(src, dst);

    k_gemm1_mma<<<(NN + 127) / 128, 256, G1_SMEM>>>(features, W1);
    k_prop128  <<<PB, 256>>>(b1);

    k_gemm2_mma<<<(NN + 127) / 128, 256, G2_SMEM>>>(W2, gamma1, beta1);
    k_prop64   <<<PB, 256>>>(b2);

    k_final    <<<(NB * 32) / 256, 256>>>(batch, gamma2, beta2, out);
}

// round 16
// speedup vs baseline: 1.5064x; 1.0280x over previous
#include <cuda_runtime.h>
#include <cuda_bf16.h>
#include <cstdint>

#define NN   100000
#define NE   1600000
#define FEAT 256
#define HID  128
#define OUTC 64
#define NB   10000
#define EPSV 1e-5f

#define NSB  ((NN + 511) / 512)   // 196 scan blocks
#define PB   2048                 // propagate grid blocks

// ---------------- device scratch (static, allocation-free) ----------------
__device__ int   g_deg[NN];
__device__ float g_dinv[NN];
__device__ int   g_rowstart[NN + 1];
__device__ int   g_cursor[NN];
__device__ int   g_col[NE];
__device__ int   g_blocksums[NSB];
__device__ int   g_blockoffs[NSB];
__device__ float g_h1[(size_t)NN * HID];   // RAW X@W1 (no dinv prescale)
__device__ float g_p1[(size_t)NN * HID];   // propagated layer1 (pre-BN)
__device__ float g_h2[(size_t)NN * OUTC];  // dinv-prescaled
__device__ float g_p2[(size_t)NN * OUTC];
__device__ float g_stats1[2 * HID];        // [sum | sumsq]
__device__ float g_stats2[2 * OUTC];

// ---- side stream + events for capture fork/join (host resources, static init)
static cudaStream_t g_s2;
static cudaEvent_t  g_evA, g_evB;
namespace {
struct SInit {
    SInit() {
        cudaStreamCreateWithFlags(&g_s2, cudaStreamNonBlocking);
        cudaEventCreateWithFlags(&g_evA, cudaEventDisableTiming);
        cudaEventCreateWithFlags(&g_evB, cudaEventDisableTiming);
    }
} s_init;
}

// ================= warp-MMA helpers (arch-neutral: ldmatrix + mma.sync) ======
__device__ __forceinline__ uint32_t smem_u32(const void* p) {
    uint32_t a;
    asm("{ .reg .u64 t; cvta.to.shared.u64 t, %1; cvt.u32.u64 %0, t; }" : "=r"(a) : "l"(p));
    return a;
}

#define LDSM4(r, addr)                                                          \
    asm volatile("ldmatrix.sync.aligned.m8n8.x4.shared.b16 {%0,%1,%2,%3}, [%4];"\
        : "=r"((r)[0]), "=r"((r)[1]), "=r"((r)[2]), "=r"((r)[3]) : "r"(addr))

#define MMAB(d, a, b0, b1)                                                      \
    asm volatile("mma.sync.aligned.m16n8k16.row.col.f32.bf16.bf16.f32 "         \
        "{%0,%1,%2,%3},{%4,%5,%6,%7},{%8,%9},{%0,%1,%2,%3};"                    \
        : "+f"((d)[0]), "+f"((d)[1]), "+f"((d)[2]), "+f"((d)[3])                \
        : "r"((a)[0]), "r"((a)[1]), "r"((a)[2]), "r"((a)[3]), "r"(b0), "r"(b1))

#define SWZ(o) ((o) ^ ((((uint32_t)(o)) >> 3) & 0x70u))

// bf16 hi/lo split of 4 fp32 -> packed (4 bf16 = 8B each)
__device__ __forceinline__ unsigned pack2(__nv_bfloat16 a, __nv_bfloat16 b) {
    __nv_bfloat162 t = __halves2bfloat162(a, b);
    return *reinterpret_cast<unsigned*>(&t);
}
__device__ __forceinline__ void bf16_split4(float4 v, uint2& hi, uint2& lo) {
    __nv_bfloat16 h0 = __float2bfloat16(v.x), h1 = __float2bfloat16(v.y);
    __nv_bfloat16 h2 = __float2bfloat16(v.z), h3 = __float2bfloat16(v.w);
    __nv_bfloat16 l0 = __float2bfloat16(v.x - __bfloat162float(h0));
    __nv_bfloat16 l1 = __float2bfloat16(v.y - __bfloat162float(h1));
    __nv_bfloat16 l2 = __float2bfloat16(v.z - __bfloat162float(h2));
    __nv_bfloat16 l3 = __float2bfloat16(v.w - __bfloat162float(h3));
    hi.x = pack2(h0, h1); hi.y = pack2(h2, h3);
    lo.x = pack2(l0, l1); lo.y = pack2(l2, l3);
}

// SMEM layouts (dynamic):
#define G1_B    0
#define G1_BSTR 32768
#define G1_A    131072
#define G1_ASTR 32768
#define G1_SMEM (131072 + 2 * 32768)    // 196608 (192KB)
#define G2_B    0
#define G2_BSTR 16384
#define G2_A    32768
#define G2_ASTR 32768
#define G2_SMEM (32768 + 2 * 32768)     // 98304 (96KB)

// ---------------- degree / CSR build ----------------
__global__ void k_init() {
    int i = blockIdx.x * blockDim.x + threadIdx.x;
    if (i < NN) g_deg[i] = 1;              // self loop
    if (i < 2 * HID)  g_stats1[i] = 0.f;
    if (i < 2 * OUTC) g_stats2[i] = 0.f;
}

__global__ void k_count(const int* __restrict__ dst) {
    int e = blockIdx.x * blockDim.x + threadIdx.x;
    if (e < NE) atomicAdd(&g_deg[dst[e]], 1);
}

__global__ void k_scan_a() {
    __shared__ int s[512];
    int t = threadIdx.x;
    int i = blockIdx.x * 512 + t;
    int v = 0;
    if (i < NN) {
        int d = g_deg[i];
        v = d - 1;                         // CSR counts exclude self loop
        g_dinv[i] = rsqrtf((float)d);      // fused dinv
    }
    s[t] = v;
    __syncthreads();
    #pragma unroll
    for (int off = 1; off < 512; off <<= 1) {
        int x = 0;
        if (t >= off) x = s[t - off];
        __syncthreads();
        s[t] += x;
        __syncthreads();
    }
    if (i < NN) g_rowstart[i] = s[t] - v;    // exclusive within block
    if (t == 511) g_blocksums[blockIdx.x] = s[511];
}

__global__ void k_scan_b() {
    __shared__ int s[256];
    int t = threadIdx.x;
    int v = (t < NSB) ? g_blocksums[t] : 0;
    s[t] = v;
    __syncthreads();
    #pragma unroll
    for (int off = 1; off < 256; off <<= 1) {
        int x = 0;
        if (t >= off) x = s[t - off];
        __syncthreads();
        s[t] += x;
        __syncthreads();
    }
    if (t < NSB) g_blockoffs[t] = s[t] - v;
}

__global__ void k_scan_c() {
    int t = threadIdx.x;
    int b = blockIdx.x;
    int i = b * 512 + t;
    if (i < NN) {
        int r = g_rowstart[i] + g_blockoffs[b];
        g_rowstart[i] = r;
        g_cursor[i] = r;
    }
    if (i == 0) g_rowstart[NN] = NE;
}

__global__ void k_fill(const int* __restrict__ src, const int* __restrict__ dst) {
    int e = blockIdx.x * blockDim.x + threadIdx.x;
    if (e >= NE) return;
    int d = dst[e];
    int p = atomicAdd(&g_cursor[d], 1);
    g_col[p] = src[e];
}

// ================= GEMM1 (mma.sync bf16 split): g_h1 = X @ W1 (raw) ===========
// BM=128, BN=128, BK=64 x 4 chunks. 8 warps: 4(M) x 2(N), warp tile 32x64.
// NOTE: no dinv in epilogue -> independent of CSR build -> runs on side stream.
__global__ __launch_bounds__(256, 1) void k_gemm1_mma(const float* __restrict__ X,
                                                      const float* __restrict__ W) {
    extern __shared__ char smem[];
    uint32_t sb = smem_u32(smem);
    const int tid = threadIdx.x, wid = tid >> 5, lane = tid & 31;
    const int bm = blockIdx.x * 128;
    const int wm = wid & 3, wn = wid >> 2;

    float acc[2][8][4];
    #pragma unroll
    for (int i = 0; i < 2; i++)
        #pragma unroll
        for (int j = 0; j < 8; j++)
            #pragma unroll
            for (int k = 0; k < 4; k++) acc[i][j][k] = 0.f;

    const int arow = wm * 32 + (lane & 15);
    const uint32_t a_off  = (uint32_t)(arow * 128);
    const uint32_t a_xor  = (uint32_t)((arow & 7) * 16);
    const uint32_t a_kb   = (uint32_t)((lane >> 4) << 4);      // 0 | 16

    const int brow = wn * 64 + (lane & 7) + ((lane >> 4) << 3);
    const uint32_t b_rowoff = (uint32_t)(brow * 128);
    const uint32_t b_xor  = (uint32_t)((brow & 7) * 16);
    const uint32_t b_kb   = (uint32_t)(((lane >> 3) & 1) << 4); // 0 | 16

    const int s_row = tid >> 4;
    const int s_kq  = (tid & 15) * 4;

    // ---- stage ALL B chunks once: B[n][k] = W1[k][n], hi/lo split, swizzled
    #pragma unroll
    for (int it = 0; it < 32; it++) {
        int id  = tid + it * 256;
        int c   = id >> 11;
        int rem = id & 2047;
        int n   = rem & 127;
        int kq  = (rem >> 7) * 4;
        const float* wp = W + (size_t)(c * 64 + kq) * HID + n;
        float4 v = make_float4(wp[0], wp[HID], wp[2 * HID], wp[3 * HID]);
        uint2 h, l; bf16_split4(v, h, l);
        uint32_t off = SWZ((uint32_t)(n * 128 + kq * 2));
        *(uint2*)(smem + G1_B + c * G1_BSTR + off)         = h;
        *(uint2*)(smem + G1_B + c * G1_BSTR + 16384 + off) = l;
    }

    // ---- prefetch chunk 0 into regs, stage to buffer 0
    float4 v[8];
    #pragma unroll
    for (int it = 0; it < 8; it++) {
        int row = s_row + it * 16;
        int gr  = bm + row;
        v[it] = (gr < NN) ? *(const float4*)(X + (size_t)gr * FEAT + s_kq)
                          : make_float4(0.f, 0.f, 0.f, 0.f);
    }
    #pragma unroll
    for (int it = 0; it < 8; it++) {
        int row = s_row + it * 16;
        uint2 h, l; bf16_split4(v[it], h, l);
        uint32_t off = SWZ((uint32_t)(row * 128 + s_kq * 2));
        *(uint2*)(smem + G1_A + off)         = h;
        *(uint2*)(smem + G1_A + 16384 + off) = l;
    }
    __syncthreads();

    for (int c = 0; c < 4; c++) {
        if (c < 3) {
            #pragma unroll
            for (int it = 0; it < 8; it++) {
                int row = s_row + it * 16;
                int gr  = bm + row;
                v[it] = (gr < NN) ? *(const float4*)(X + (size_t)gr * FEAT + (c + 1) * 64 + s_kq)
                                  : make_float4(0.f, 0.f, 0.f, 0.f);
            }
        }

        const uint32_t abuf = sb + G1_A + (c & 1) * G1_ASTR;
        const uint32_t a_base = abuf + a_off;
        const uint32_t bb = sb + G1_B + c * G1_BSTR + b_rowoff;
        #pragma unroll
        for (int ks = 0; ks < 4; ks++) {
            uint32_t ah[2][4], al[2][4], bh[4][4], bl[4][4];
            uint32_t ka = ((uint32_t)(ks * 32) + a_kb) ^ a_xor;
            LDSM4(ah[0], a_base + ka);
            LDSM4(ah[1], a_base + 2048 + ka);
            LDSM4(al[0], a_base + 16384 + ka);
            LDSM4(al[1], a_base + 16384 + 2048 + ka);
            uint32_t kb = ((uint32_t)(ks * 32) + b_kb) ^ b_xor;
            #pragma unroll
            for (int p = 0; p < 4; p++) {
                LDSM4(bh[p], bb + p * 2048 + kb);
                LDSM4(bl[p], bb + 16384 + p * 2048 + kb);
            }
            #pragma unroll
            for (int mt = 0; mt < 2; mt++)
                #pragma unroll
                for (int nt = 0; nt < 8; nt++) {
                    uint32_t b0h = bh[nt >> 1][(nt & 1) * 2], b1h = bh[nt >> 1][(nt & 1) * 2 + 1];
                    uint32_t b0l = bl[nt >> 1][(nt & 1) * 2], b1l = bl[nt >> 1][(nt & 1) * 2 + 1];
                    MMAB(acc[mt][nt], ah[mt], b0h, b1h);
                    MMAB(acc[mt][nt], ah[mt], b0l, b1l);
                    MMAB(acc[mt][nt], al[mt], b0h, b1h);
                }
        }

        if (c < 3) {
            char* dst = smem + G1_A + ((c + 1) & 1) * G1_ASTR;
            #pragma unroll
            for (int it = 0; it < 8; it++) {
                int row = s_row + it * 16;
                uint2 h, l; bf16_split4(v[it], h, l);
                uint32_t off = SWZ((uint32_t)(row * 128 + s_kq * 2));
                *(uint2*)(dst + off)         = h;
                *(uint2*)(dst + 16384 + off) = l;
            }
        }
        __syncthreads();
    }

    // ---- epilogue: write RAW g_h1 (dinv applied during propagation)
    #pragma unroll
    for (int mt = 0; mt < 2; mt++) {
        int r0 = bm + wm * 32 + mt * 16 + (lane >> 2);
        int r1 = r0 + 8;
        #pragma unroll
        for (int nt = 0; nt < 8; nt++) {
            int col = wn * 64 + nt * 8 + (lane & 3) * 2;
            if (r0 < NN) {
                float2 q; q.x = acc[mt][nt][0]; q.y = acc[mt][nt][1];
                *(float2*)(g_h1 + (size_t)r0 * HID + col) = q;
            }
            if (r1 < NN) {
                float2 q; q.x = acc[mt][nt][2]; q.y = acc[mt][nt][3];
                *(float2*)(g_h1 + (size_t)r1 * HID + col) = q;
            }
        }
    }
}

// ------- propagate layer1 (+fused BN stats): warp/node, grid-stride ---------
// h1 is raw; weight each gathered row by dinv[s], self by dinv[v].
__global__ __launch_bounds__(256) void k_prop128(const float* __restrict__ bias) {
    int tid = threadIdx.x, lane = tid & 31, wid = tid >> 5;
    const float4* hp = (const float4*)g_h1;
    float4 b = ((const float4*)bias)[lane];
    float4 s1 = make_float4(0.f, 0.f, 0.f, 0.f);
    float4 s2 = make_float4(0.f, 0.f, 0.f, 0.f);

    for (int vtx = blockIdx.x * 8 + wid; vtx < NN; vtx += PB * 8) {
        float dv = g_dinv[vtx];
        float4 h = hp[(size_t)vtx * 32 + lane];
        float4 acc0, acc1;
        acc0.x = dv * h.x; acc0.y = dv * h.y; acc0.z = dv * h.z; acc0.w = dv * h.w;
        acc1 = make_float4(0.f, 0.f, 0.f, 0.f);
        int beg = g_rowstart[vtx], end = g_rowstart[vtx + 1];
        int j = beg;
        for (; j + 2 <= end; j += 2) {
            int sa = __ldg(&g_col[j]), sbv = __ldg(&g_col[j + 1]);
            float da = __ldg(&g_dinv[sa]), db = __ldg(&g_dinv[sbv]);
            float4 x0 = hp[(size_t)sa * 32 + lane];
            float4 x1 = hp[(size_t)sbv * 32 + lane];
            acc0.x = fmaf(da, x0.x, acc0.x); acc0.y = fmaf(da, x0.y, acc0.y);
            acc0.z = fmaf(da, x0.z, acc0.z); acc0.w = fmaf(da, x0.w, acc0.w);
            acc1.x = fmaf(db, x1.x, acc1.x); acc1.y = fmaf(db, x1.y, acc1.y);
            acc1.z = fmaf(db, x1.z, acc1.z); acc1.w = fmaf(db, x1.w, acc1.w);
        }
        if (j < end) {
            int sa = __ldg(&g_col[j]);
            float da = __ldg(&g_dinv[sa]);
            float4 x = hp[(size_t)sa * 32 + lane];
            acc0.x = fmaf(da, x.x, acc0.x); acc0.y = fmaf(da, x.y, acc0.y);
            acc0.z = fmaf(da, x.z, acc0.z); acc0.w = fmaf(da, x.w, acc0.w);
        }
        float4 o;
        o.x = fmaf(acc0.x + acc1.x, dv, b.x);
        o.y = fmaf(acc0.y + acc1.y, dv, b.y);
        o.z = fmaf(acc0.z + acc1.z, dv, b.z);
        o.w = fmaf(acc0.w + acc1.w, dv, b.w);
        ((float4*)g_p1)[(size_t)vtx * 32 + lane] = o;
        s1.x += o.x; s1.y += o.y; s1.z += o.z; s1.w += o.w;
        s2.x += o.x * o.x; s2.y += o.y * o.y; s2.z += o.z * o.z; s2.w += o.w * o.w;
    }

    __shared__ float4 sh1[8][32], sh2[8][32];
    sh1[wid][lane] = s1; sh2[wid][lane] = s2;
    __syncthreads();
    if (wid == 0) {
        float4 t1 = sh1[0][lane], t2 = sh2[0][lane];
        #pragma unroll
        for (int w = 1; w < 8; w++) {
            float4 a1 = sh1[w][lane], a2 = sh2[w][lane];
            t1.x += a1.x; t1.y += a1.y; t1.z += a1.z; t1.w += a1.w;
            t2.x += a2.x; t2.y += a2.y; t2.z += a2.z; t2.w += a2.w;
        }
        int c = lane * 4;
        atomicAdd(&g_stats1[c + 0], t1.x);
        atomicAdd(&g_stats1[c + 1], t1.y);
        atomicAdd(&g_stats1[c + 2], t1.z);
        atomicAdd(&g_stats1[c + 3], t1.w);
        atomicAdd(&g_stats1[HID + c + 0], t2.x);
        atomicAdd(&g_stats1[HID + c + 1], t2.y);
        atomicAdd(&g_stats1[HID + c + 2], t2.z);
        atomicAdd(&g_stats1[HID + c + 3], t2.w);
    }
}

// ================= GEMM2: g_h2 = dinv * (relu(BN1(p1)) @ W2) ==================
__global__ __launch_bounds__(256, 1) void k_gemm2_mma(const float* __restrict__ W2,
                                                      const float* __restrict__ gamma1,
                                                      const float* __restrict__ beta1) {
    extern __shared__ char smem[];
    __shared__ float bnA[HID], bnB[HID];
    uint32_t sb = smem_u32(smem);
    const int tid = threadIdx.x, wid = tid >> 5, lane = tid & 31;
    const int bm = blockIdx.x * 128;
    const int wm = wid & 3, wn = wid >> 2;

    if (tid < HID) {
        float s  = g_stats1[tid], ss = g_stats1[HID + tid];
        float mu = s * (1.0f / NN);
        float var = ss * (1.0f / NN) - mu * mu;
        float rs = rsqrtf(var + EPSV);
        float ga = gamma1[tid];
        bnA[tid] = rs * ga;
        bnB[tid] = beta1[tid] - mu * rs * ga;
    }

    float acc[2][4][4];
    #pragma unroll
    for (int i = 0; i < 2; i++)
        #pragma unroll
        for (int j = 0; j < 4; j++)
            #pragma unroll
            for (int k = 0; k < 4; k++) acc[i][j][k] = 0.f;

    const int arow = wm * 32 + (lane & 15);
    const uint32_t a_off  = (uint32_t)(arow * 128);
    const uint32_t a_xor  = (uint32_t)((arow & 7) * 16);
    const uint32_t a_kb   = (uint32_t)((lane >> 4) << 4);

    const int brow = wn * 32 + (lane & 7) + ((lane >> 4) << 3);
    const uint32_t b_rowoff = (uint32_t)(brow * 128);
    const uint32_t b_xor  = (uint32_t)((brow & 7) * 16);
    const uint32_t b_kb   = (uint32_t)(((lane >> 3) & 1) << 4);

    const int s_row = tid >> 4;
    const int s_kq  = (tid & 15) * 4;

    #pragma unroll
    for (int it = 0; it < 8; it++) {
        int id  = tid + it * 256;
        int c   = id >> 10;
        int rem = id & 1023;
        int n   = rem & 63;
        int kq  = (rem >> 6) * 4;
        const float* wp = W2 + (size_t)(c * 64 + kq) * OUTC + n;
        float4 v = make_float4(wp[0], wp[OUTC], wp[2 * OUTC], wp[3 * OUTC]);
        uint2 h, l; bf16_split4(v, h, l);
        uint32_t off = SWZ((uint32_t)(n * 128 + kq * 2));
        *(uint2*)(smem + G2_B + c * G2_BSTR + off)        = h;
        *(uint2*)(smem + G2_B + c * G2_BSTR + 8192 + off) = l;
    }
    __syncthreads();   // bn coeffs + B ready

    float4 v[8];
    #pragma unroll
    for (int it = 0; it < 8; it++) {
        int row = s_row + it * 16;
        int gr  = bm + row;
        float4 t = make_float4(0.f, 0.f, 0.f, 0.f);
        if (gr < NN) {
            t = *(const float4*)(g_p1 + (size_t)gr * HID + s_kq);
            t.x = fmaxf(0.f, fmaf(t.x, bnA[s_kq + 0], bnB[s_kq + 0]));
            t.y = fmaxf(0.f, fmaf(t.y, bnA[s_kq + 1], bnB[s_kq + 1]));
            t.z = fmaxf(0.f, fmaf(t.z, bnA[s_kq + 2], bnB[s_kq + 2]));
            t.w = fmaxf(0.f, fmaf(t.w, bnA[s_kq + 3], bnB[s_kq + 3]));
        }
        v[it] = t;
    }
    #pragma unroll
    for (int it = 0; it < 8; it++) {
        int row = s_row + it * 16;
        uint2 h, l; bf16_split4(v[it], h, l);
        uint32_t off = SWZ((uint32_t)(row * 128 + s_kq * 2));
        *(uint2*)(smem + G2_A + off)         = h;
        *(uint2*)(smem + G2_A + 16384 + off) = l;
    }
    __syncthreads();

    for (int c = 0; c < 2; c++) {
        if (c < 1) {
            #pragma unroll
            for (int it = 0; it < 8; it++) {
                int row = s_row + it * 16;
                int gr  = bm + row;
                int kc  = 64 + s_kq;
                float4 t = make_float4(0.f, 0.f, 0.f, 0.f);
                if (gr < NN) {
                    t = *(const float4*)(g_p1 + (size_t)gr * HID + kc);
                    t.x = fmaxf(0.f, fmaf(t.x, bnA[kc + 0], bnB[kc + 0]));
                    t.y = fmaxf(0.f, fmaf(t.y, bnA[kc + 1], bnB[kc + 1]));
                    t.z = fmaxf(0.f, fmaf(t.z, bnA[kc + 2], bnB[kc + 2]));
                    t.w = fmaxf(0.f, fmaf(t.w, bnA[kc + 3], bnB[kc + 3]));
                }
                v[it] = t;
            }
        }

        const uint32_t abuf = sb + G2_A + (c & 1) * G2_ASTR;
        const uint32_t a_base = abuf + a_off;
        const uint32_t bb = sb + G2_B + c * G2_BSTR + b_rowoff;
        #pragma unroll
        for (int ks = 0; ks < 4; ks++) {
            uint32_t ah[2][4], al[2][4], bh[2][4], bl[2][4];
            uint32_t ka = ((uint32_t)(ks * 32) + a_kb) ^ a_xor;
            LDSM4(ah[0], a_base + ka);
            LDSM4(ah[1], a_base + 2048 + ka);
            LDSM4(al[0], a_base + 16384 + ka);
            LDSM4(al[1], a_base + 16384 + 2048 + ka);
            uint32_t kb = ((uint32_t)(ks * 32) + b_kb) ^ b_xor;
            #pragma unroll
            for (int p = 0; p < 2; p++) {
                LDSM4(bh[p], bb + p * 2048 + kb);
                LDSM4(bl[p], bb + 8192 + p * 2048 + kb);
            }
            #pragma unroll
            for (int mt = 0; mt < 2; mt++)
                #pragma unroll
                for (int nt = 0; nt < 4; nt++) {
                    uint32_t b0h = bh[nt >> 1][(nt & 1) * 2], b1h = bh[nt >> 1][(nt & 1) * 2 + 1];
                    uint32_t b0l = bl[nt >> 1][(nt & 1) * 2], b1l = bl[nt >> 1][(nt & 1) * 2 + 1];
                    MMAB(acc[mt][nt], ah[mt], b0h, b1h);
                    MMAB(acc[mt][nt], ah[mt], b0l, b1l);
                    MMAB(acc[mt][nt], al[mt], b0h, b1h);
                }
        }

        if (c < 1) {
            char* dst = smem + G2_A + G2_ASTR;
            #pragma unroll
            for (int it = 0; it < 8; it++) {
                int row = s_row + it * 16;
                uint2 h, l; bf16_split4(v[it], h, l);
                uint32_t off = SWZ((uint32_t)(row * 128 + s_kq * 2));
                *(uint2*)(dst + off)         = h;
                *(uint2*)(dst + 16384 + off) = l;
            }
        }
        __syncthreads();
    }

    #pragma unroll
    for (int mt = 0; mt < 2; mt++) {
        int r0 = bm + wm * 32 + mt * 16 + (lane >> 2);
        int r1 = r0 + 8;
        float dv0 = (r0 < NN) ? g_dinv[r0] : 0.f;
        float dv1 = (r1 < NN) ? g_dinv[r1] : 0.f;
        #pragma unroll
        for (int nt = 0; nt < 4; nt++) {
            int col = wn * 32 + nt * 8 + (lane & 3) * 2;
            if (r0 < NN) {
                float2 q; q.x = acc[mt][nt][0] * dv0; q.y = acc[mt][nt][1] * dv0;
                *(float2*)(g_h2 + (size_t)r0 * OUTC + col) = q;
            }
            if (r1 < NN) {
                float2 q; q.x = acc[mt][nt][2] * dv1; q.y = acc[mt][nt][3] * dv1;
                *(float2*)(g_h2 + (size_t)r1 * OUTC + col) = q;
            }
        }
    }
}

// ------- propagate layer2 (+fused BN stats): warp/node, grid-stride ---------
__global__ __launch_bounds__(256) void k_prop64(const float* __restrict__ bias) {
    int tid = threadIdx.x, lane = tid & 31, wid = tid >> 5;
    const float2* hp = (const float2*)g_h2;
    float2 b = ((const float2*)bias)[lane];
    float2 s1 = make_float2(0.f, 0.f), s2 = make_float2(0.f, 0.f);

    for (int vtx = blockIdx.x * 8 + wid; vtx < NN; vtx += PB * 8) {
        float2 acc0 = hp[(size_t)vtx * 32 + lane];
        float2 acc1 = make_float2(0.f, 0.f);
        int beg = g_rowstart[vtx], end = g_rowstart[vtx + 1];
        int j = beg;
        for (; j + 2 <= end; j += 2) {
            int sa = __ldg(&g_col[j]), sbv = __ldg(&g_col[j + 1]);
            float2 x0 = hp[(size_t)sa * 32 + lane];
            float2 x1 = hp[(size_t)sbv * 32 + lane];
            acc0.x += x0.x; acc0.y += x0.y;
            acc1.x += x1.x; acc1.y += x1.y;
        }
        if (j < end) {
            int sa = __ldg(&g_col[j]);
            float2 x = hp[(size_t)sa * 32 + lane];
            acc0.x += x.x; acc0.y += x.y;
        }
        float dv = g_dinv[vtx];
        float2 o;
        o.x = fmaf(acc0.x + acc1.x, dv, b.x);
        o.y = fmaf(acc0.y + acc1.y, dv, b.y);
        ((float2*)g_p2)[(size_t)vtx * 32 + lane] = o;
        s1.x += o.x; s1.y += o.y;
        s2.x += o.x * o.x; s2.y += o.y * o.y;
    }

    __shared__ float2 sh1[8][32], sh2[8][32];
    sh1[wid][lane] = s1; sh2[wid][lane] = s2;
    __syncthreads();
    if (wid == 0) {
        float2 t1 = sh1[0][lane], t2 = sh2[0][lane];
        #pragma unroll
        for (int w = 1; w < 8; w++) {
            float2 a1 = sh1[w][lane], a2 = sh2[w][lane];
            t1.x += a1.x; t1.y += a1.y;
            t2.x += a2.x; t2.y += a2.y;
        }
        int c = lane * 2;
        atomicAdd(&g_stats2[c + 0], t1.x);
        atomicAdd(&g_stats2[c + 1], t1.y);
        atomicAdd(&g_stats2[OUTC + c + 0], t2.x);
        atomicAdd(&g_stats2[OUTC + c + 1], t2.y);
    }
}

// ---------------- final: gather batch, BN2+relu+log_softmax ----------------
__global__ void k_final(const int* __restrict__ bn,
                        const float* __restrict__ gamma2,
                        const float* __restrict__ beta2,
                        float* __restrict__ out) {
    int gt = blockIdx.x * blockDim.x + threadIdx.x;
    int w = gt >> 5;
    if (w >= NB) return;
    int lane = gt & 31;
    int node = bn[w];
    float2 v = ((const float2*)g_p2)[(size_t)node * 32 + lane];
    int c0 = lane * 2, c1 = c0 + 1;
    float x0, x1;
    {
        float s = g_stats2[c0], ss = g_stats2[OUTC + c0];
        float mu = s * (1.f / NN);
        float var = ss * (1.f / NN) - mu * mu;
        float rs = rsqrtf(var + EPSV);
        x0 = fmaxf(0.f, (v.x - mu) * rs * gamma2[c0] + beta2[c0]);
    }
    {
        float s = g_stats2[c1], ss = g_stats2[OUTC + c1];
        float mu = s * (1.f / NN);
        float var = ss * (1.f / NN) - mu * mu;
        float rs = rsqrtf(var + EPSV);
        x1 = fmaxf(0.f, (v.y - mu) * rs * gamma2[c1] + beta2[c1]);
    }
    float m = fmaxf(x0, x1);
    #pragma unroll
    for (int o = 16; o; o >>= 1) m = fmaxf(m, __shfl_xor_sync(0xffffffffu, m, o));
    float e = expf(x0 - m) + expf(x1 - m);
    #pragma unroll
    for (int o = 16; o; o >>= 1) e += __shfl_xor_sync(0xffffffffu, e, o);
    float l = m + logf(e);
    float2 r;
    r.x = x0 - l; r.y = x1 - l;
    ((float2*)out)[(size_t)w * 32 + lane] = r;
}

// ---------------- launch ----------------
extern "C" void kernel_launch(void* const* d_in, const int* in_sizes, int n_in,
                              void* d_out, int out_size) {
    const float* features = (const float*)d_in[0];
    const int*   ei       = (const int*)d_in[1];
    const int*   batch    = (const int*)d_in[2];
    const float* W1       = (const float*)d_in[3];
    const float* b1       = (const float*)d_in[4];
    const float* gamma1   = (const float*)d_in[5];
    const float* beta1    = (const float*)d_in[6];
    const float* W2       = (const float*)d_in[7];
    const float* b2       = (const float*)d_in[8];
    const float* gamma2   = (const float*)d_in[9];
    const float* beta2    = (const float*)d_in[10];
    const int* src = ei;
    const int* dst = ei + NE;
    float* out = (float*)d_out;

    cudaFuncSetAttribute(k_gemm1_mma, cudaFuncAttributeMaxDynamicSharedMemorySize, G1_SMEM);
    cudaFuncSetAttribute(k_gemm2_mma, cudaFuncAttributeMaxDynamicSharedMemorySize, G2_SMEM);

    // fork: GEMM1 (independent of CSR build) runs on side stream g_s2
    cudaEventRecord(g_evA, 0);
    cudaStreamWaitEvent(g_s2, g_evA, 0);
    k_gemm1_mma<<<(NN + 127) / 128, 256, G1_SMEM, g_s2>>>(features, W1);
    cudaEventRecord(g_evB, g_s2);

    // CSR build on main stream (overlaps with GEMM1)
    k_init  <<<(NN + 255) / 256, 256>>>();
    k_count <<<(NE + 255) / 256, 256>>>(dst);
    k_scan_a<<<NSB, 512>>>();
    k_scan_b<<<1, 256>>>();
    k_scan_c<<<NSB, 512>>>();
    k_fill  <<<(NE + 255) / 256, 256>>>(src, dst);

    // join: propagation needs both GEMM1 output and CSR
    cudaStreamWaitEvent(0, g_evB, 0);
    k_prop128  <<<PB, 256>>>(b1);

    k_gemm2_mma<<<(NN + 127) / 128, 256, G2_SMEM>>>(W2, gamma1, beta1);
    k_prop64   <<<PB, 256>>>(b2);

    k_final    <<<(NB * 32) / 256, 256>>>(batch, gamma2, beta2, out);
}